// round 14
// baseline (speedup 1.0000x reference)
#include <cuda_runtime.h>
#include <cuda_fp16.h>
#include <cstdint>
#include <math.h>

// ---------------- problem constants ----------------
#define S_LEN 2048
#define HID   4096
#define NH    32
#define NKV   8
#define HD    128
#define QS    (NH * HD)          // 4096
#define KVS   (NKV * HD)         // 1024
#define QKV_N (QS + 2 * KVS)     // 6144
#define SCALE 0.08838834764831845f  // 128^-0.5
#define LOG2E 1.4426950408889634f

// ---------------- scratch (static device globals; no allocs) ----------------
__device__ float g_qkv[S_LEN * QKV_N];       // QKV projection output [S, 6144]

// fp16 operands
__device__ __half g_ah[S_LEN * HID];         // activation hi [M,K] (hidden, then attn)
__device__ __half g_wqh[QKV_N * HID];        // w_qkv^T hi [N,K]
__device__ __half g_woh[HID * QS];           // w_o^T hi   [N,K]

// fp16 split Q/K/V, head-major [h][s][d] (flash keeps full precision)
__device__ __half g_qh[NH * S_LEN * HD];
__device__ __half g_ql[NH * S_LEN * HD];
__device__ __half g_kh[NKV * S_LEN * HD];
__device__ __half g_kl[NKV * S_LEN * HD];
__device__ __half g_vh[NKV * S_LEN * HD];
__device__ __half g_vl[NKV * S_LEN * HD];

// ==========================================================================
// small PTX helpers
// ==========================================================================
__device__ __forceinline__ uint32_t smem_to_u32(const void* p) {
    uint32_t a;
    asm("{ .reg .u64 t; cvta.to.shared.u64 t, %1; cvt.u32.u64 %0, t; }"
        : "=r"(a) : "l"(p));
    return a;
}
__device__ __forceinline__ void cp_async16(uint32_t dst, const void* src) {
    asm volatile("cp.async.cg.shared.global [%0], [%1], 16;"
                 :: "r"(dst), "l"(src) : "memory");
}
#define CP_COMMIT() asm volatile("cp.async.commit_group;" ::: "memory")
#define CP_WAIT(n)  asm volatile("cp.async.wait_group %0;" :: "n"(n) : "memory")

__device__ __forceinline__ void ldsm_x4(uint32_t* r, uint32_t addr) {
    asm volatile("ldmatrix.sync.aligned.m8n8.x4.shared.b16 {%0,%1,%2,%3}, [%4];"
                 : "=r"(r[0]), "=r"(r[1]), "=r"(r[2]), "=r"(r[3]) : "r"(addr));
}
__device__ __forceinline__ void ldsm_x2(uint32_t* r, uint32_t addr) {
    asm volatile("ldmatrix.sync.aligned.m8n8.x2.shared.b16 {%0,%1}, [%2];"
                 : "=r"(r[0]), "=r"(r[1]) : "r"(addr));
}
__device__ __forceinline__ void ldsm_x2_trans(uint32_t* r, uint32_t addr) {
    asm volatile("ldmatrix.sync.aligned.m8n8.x2.trans.shared.b16 {%0,%1}, [%2];"
                 : "=r"(r[0]), "=r"(r[1]) : "r"(addr));
}
__device__ __forceinline__ void mma16816(float* c, const uint32_t* a, const uint32_t* b) {
    asm volatile("mma.sync.aligned.m16n8k16.row.col.f32.f16.f16.f32 "
                 "{%0,%1,%2,%3}, {%4,%5,%6,%7}, {%8,%9}, {%0,%1,%2,%3};"
                 : "+f"(c[0]), "+f"(c[1]), "+f"(c[2]), "+f"(c[3])
                 : "r"(a[0]), "r"(a[1]), "r"(a[2]), "r"(a[3]),
                   "r"(b[0]), "r"(b[1]));
}
__device__ __forceinline__ uint32_t packh2(float a, float b) {
    __half2 h = __floats2half2_rn(a, b);
    return *reinterpret_cast<uint32_t*>(&h);
}
// fast 2^t on FMA/ALU pipes (avoids MUFU bottleneck); rel err ~1e-7
__device__ __forceinline__ float fast_exp2(float t) {
    t = fmaxf(t, -126.0f);
    float z = t + 12582912.0f;                       // round-to-nearest-int trick
    int   n = __float_as_int(z) - 0x4B400000;
    float f = t - (z - 12582912.0f);                 // f in [-0.5, 0.5]
    float p = 1.5435339e-4f;
    p = fmaf(p, f, 1.3333558e-3f);
    p = fmaf(p, f, 9.6181291e-3f);
    p = fmaf(p, f, 5.5504109e-2f);
    p = fmaf(p, f, 2.4022651e-1f);
    p = fmaf(p, f, 6.9314718e-1f);
    p = fmaf(p, f, 1.0f);
    return __int_as_float(__float_as_int(p) + (n << 23));
}

#define ROW_B   80
#define TILE_B  (128 * ROW_B)         // 10240

// ==========================================================================
// 1-term fp16 GEMM: C = Ah[M,K] @ Bh[N,K]^T
// 8 warps, warp tile 64x32, 2-stage (20KB/stage) -> high occupancy.
// Used for BOTH QKV projection and O projection.
// ==========================================================================
#define STAGE1_B (2 * TILE_B)          // 20480
#define GEMM1_SMEM (2 * STAGE1_B)      // 40960

__global__ __launch_bounds__(256) void gemm_hmma_hi(
    const __half* __restrict__ Ah, const __half* __restrict__ Bh,
    float* __restrict__ C, int Nglob, int Kglob)
{
    extern __shared__ __align__(128) char smem[];
    const uint32_t sbase = smem_to_u32(smem);
    const int tid  = threadIdx.x;
    const int wid  = tid >> 5;
    const int lane = tid & 31;
    const int brow = blockIdx.y * 128;
    const int bcol = blockIdx.x * 128;
    const int NC   = Kglob / 32;

    const int wm = (wid >> 2) * 64;
    const int wn = (wid & 3) * 32;

    const __half* __restrict__ srcs[2] = { Ah, Bh };

    float acc[4][4][4];
#pragma unroll
    for (int i = 0; i < 4; i++)
#pragma unroll
        for (int j = 0; j < 4; j++)
#pragma unroll
            for (int e = 0; e < 4; e++) acc[i][j][e] = 0.0f;

    auto load_stage = [&](int s, int c) {
        const int k0 = c * 32;
        const uint32_t stage = sbase + s * STAGE1_B;
#pragma unroll
        for (int m = 0; m < 2; m++) {
            const int rowbase = (m < 1) ? brow : bcol;
            const __half* src = srcs[m];
#pragma unroll
            for (int t = 0; t < 2; t++) {
                int e  = tid + t * 256;
                int r  = e >> 2;
                int cc = e & 3;
                const void* g = src + (size_t)(rowbase + r) * Kglob + k0 + cc * 8;
                cp_async16(stage + m * TILE_B + r * ROW_B + cc * 16, g);
            }
        }
    };

    load_stage(0, 0);
    CP_COMMIT();

    for (int c = 0; c < NC; c++) {
        if (c + 1 < NC) { load_stage((c + 1) & 1, c + 1); CP_COMMIT(); CP_WAIT(1); }
        else            { CP_WAIT(0); }
        __syncthreads();

        const uint32_t st = sbase + (c & 1) * STAGE1_B;
        const uint32_t a_base = st;
        const uint32_t b_base = st + TILE_B;

        const int arow = wm + (lane & 15);
        const int acol16 = (lane >> 4) * 16;
        const int brow8 = wn + (lane & 7);
        const int bcol16 = ((lane >> 3) & 1) * 16;

#pragma unroll
        for (int ks = 0; ks < 2; ks++) {
            const int koff = ks * 32;
            uint32_t ahf[4][4], bhf[4][2];
#pragma unroll
            for (int i = 0; i < 4; i++)
                ldsm_x4(ahf[i], a_base + (arow + i * 16) * ROW_B + acol16 + koff);
#pragma unroll
            for (int j = 0; j < 4; j++)
                ldsm_x2(bhf[j], b_base + (brow8 + j * 8) * ROW_B + bcol16 + koff);
#pragma unroll
            for (int i = 0; i < 4; i++)
#pragma unroll
                for (int j = 0; j < 4; j++)
                    mma16816(acc[i][j], ahf[i], bhf[j]);
        }
        __syncthreads();
    }

    const int erow = brow + wm + (lane >> 2);
    const int ecol = bcol + wn + (lane & 3) * 2;
#pragma unroll
    for (int i = 0; i < 4; i++) {
#pragma unroll
        for (int j = 0; j < 4; j++) {
            float* p0 = C + (size_t)(erow + i * 16) * Nglob + ecol + j * 8;
            float* p1 = C + (size_t)(erow + i * 16 + 8) * Nglob + ecol + j * 8;
            *(float2*)p0 = make_float2(acc[i][j][0], acc[i][j][1]);
            *(float2*)p1 = make_float2(acc[i][j][2], acc[i][j][3]);
        }
    }
}

// ==========================================================================
// fp32 -> fp16 (hi only)
// ==========================================================================
__global__ __launch_bounds__(256) void convert_hi(
    const float* __restrict__ x, __half* __restrict__ hi, int n4)
{
    int i = blockIdx.x * 256 + threadIdx.x;
    if (i >= n4) return;
    float4 v = ((const float4*)x)[i];
    __half hs[4];
    hs[0] = __float2half_rn(v.x);
    hs[1] = __float2half_rn(v.y);
    hs[2] = __float2half_rn(v.z);
    hs[3] = __float2half_rn(v.w);
    *(uint2*)(hi + i * 4) = *(uint2*)hs;
}

// ==========================================================================
// W[K,N] fp32 -> W^T[N,K] fp16 (hi only)
// ==========================================================================
__global__ __launch_bounds__(256) void transpose_hi(
    const float* __restrict__ W, __half* __restrict__ th, int K, int N)
{
    __shared__ float t[32][33];
    const int bx = blockIdx.x * 32;
    const int by = blockIdx.y * 32;
    const int tx = threadIdx.x;
    const int ty = threadIdx.y;
#pragma unroll
    for (int i = 0; i < 32; i += 8)
        t[ty + i][tx] = W[(size_t)(by + ty + i) * N + bx + tx];
    __syncthreads();
#pragma unroll
    for (int i = 0; i < 32; i += 8) {
        float v = t[tx][ty + i];
        th[(size_t)(bx + ty + i) * K + by + tx] = __float2half_rn(v);
    }
}

// ==========================================================================
// RoPE + split -> fp16 hi/lo Q/K/V, head-major
// ==========================================================================
__global__ __launch_bounds__(256) void rope_split_kernel(const int* __restrict__ positions)
{
    const int s   = blockIdx.x;
    const int tid = threadIdx.x;
    __shared__ float cs[64], sn[64];

    if (tid < 64) {
        float inv_freq = powf(10000.0f, -((float)(2 * tid)) / 128.0f);
        float ang = (float)positions[s] * inv_freq;
        cs[tid] = cosf(ang);
        sn[tid] = sinf(ang);
    }
    __syncthreads();

    const float* row = g_qkv + (size_t)s * QKV_N;

    for (int idx = tid; idx < NH * 64; idx += 256) {
        int h = idx >> 6, d = idx & 63;
        float x1 = row[h * HD + d];
        float x2 = row[h * HD + d + 64];
        float a = x1 * cs[d] - x2 * sn[d];
        float b = x2 * cs[d] + x1 * sn[d];
        size_t o = ((size_t)h * S_LEN + s) * HD;
        __half ha = __float2half_rn(a), hb = __float2half_rn(b);
        g_qh[o + d]      = ha;
        g_qh[o + d + 64] = hb;
        g_ql[o + d]      = __float2half_rn(a - __half2float(ha));
        g_ql[o + d + 64] = __float2half_rn(b - __half2float(hb));
    }
    for (int idx = tid; idx < NKV * 64; idx += 256) {
        int h = idx >> 6, d = idx & 63;
        const float* kr = row + QS;
        float x1 = kr[h * HD + d];
        float x2 = kr[h * HD + d + 64];
        float a = x1 * cs[d] - x2 * sn[d];
        float b = x2 * cs[d] + x1 * sn[d];
        size_t o = ((size_t)h * S_LEN + s) * HD;
        __half ha = __float2half_rn(a), hb = __float2half_rn(b);
        g_kh[o + d]      = ha;
        g_kh[o + d + 64] = hb;
        g_kl[o + d]      = __float2half_rn(a - __half2float(ha));
        g_kl[o + d + 64] = __float2half_rn(b - __half2float(hb));
    }
    for (int idx = tid; idx < NKV * HD; idx += 256) {
        int h = idx >> 7, d = idx & 127;
        float v = row[QS + KVS + h * HD + d];
        size_t o = ((size_t)h * S_LEN + s) * HD + d;
        __half hv = __float2half_rn(v);
        g_vh[o] = hv;
        g_vl[o] = __float2half_rn(v - __half2float(hv));
    }
}

// ==========================================================================
// HMMA flash attention: BR=128, BC=64, 8 warps, causal GQA.
// Full 3-term split math (error reserve). Heaviest q-tiles first.
// Epilogue writes attn hi into g_ah for the 1-term O-GEMM.
// ==========================================================================
#define FROW 272
#define FQ_H 0
#define FQ_L (128 * FROW)
#define FSTAGE0 (2 * 128 * FROW)
#define FSTAGE_B (4 * 64 * FROW)
#define FK_H 0
#define FK_L (64 * FROW)
#define FV_H (2 * 64 * FROW)
#define FV_L (3 * 64 * FROW)
#define FLASH_SMEM (FSTAGE0 + 2 * FSTAGE_B)

__global__ __launch_bounds__(256, 1) void flash_hmma_kernel()
{
    extern __shared__ __align__(128) char smem[];
    const uint32_t sbase = smem_to_u32(smem);
    const int tid  = threadIdx.x;
    const int wid  = tid >> 5;
    const int lane = tid & 31;
    const int qt   = gridDim.x - 1 - blockIdx.x;   // heavy tiles launch first
    const int h    = blockIdx.y;
    const int kvh  = h >> 2;
    const int qbase = qt * 128;
    const int wr   = wid * 16;
    const int jlast = 2 * qt + 1;

    const __half* Qhg = g_qh + ((size_t)h * S_LEN + qbase) * HD;
    const __half* Qlg = g_ql + ((size_t)h * S_LEN + qbase) * HD;
    const __half* Khg = g_kh + (size_t)kvh * S_LEN * HD;
    const __half* Klg = g_kl + (size_t)kvh * S_LEN * HD;
    const __half* Vhg = g_vh + (size_t)kvh * S_LEN * HD;
    const __half* Vlg = g_vl + (size_t)kvh * S_LEN * HD;

    {
#pragma unroll
        for (int t = 0; t < 8; t++) {
            int e = tid + t * 256;
            int r = e >> 4, c = e & 15;
            cp_async16(sbase + FQ_H + r * FROW + c * 16, Qhg + r * HD + c * 8);
        }
#pragma unroll
        for (int t = 0; t < 8; t++) {
            int e = tid + t * 256;
            int r = e >> 4, c = e & 15;
            cp_async16(sbase + FQ_L + r * FROW + c * 16, Qlg + r * HD + c * 8);
        }
    }

    auto load_stage = [&](int s, int jt) {
        const uint32_t stage = sbase + FSTAGE0 + s * FSTAGE_B;
        const int kbase = jt * 64;
        const __half* gs[4] = { Khg, Klg, Vhg, Vlg };
        const uint32_t off[4] = { FK_H, FK_L, FV_H, FV_L };
#pragma unroll
        for (int m = 0; m < 4; m++) {
#pragma unroll
            for (int t = 0; t < 4; t++) {
                int e = tid + t * 256;
                int r = e >> 4, c = e & 15;
                cp_async16(stage + off[m] + r * FROW + c * 16,
                           gs[m] + (size_t)(kbase + r) * HD + c * 8);
            }
        }
    };

    load_stage(0, 0);
    CP_COMMIT();

    float oacc[16][4];
    float m0 = -1e30f, m1 = -1e30f, l0 = 0.0f, l1 = 0.0f;
#pragma unroll
    for (int nt = 0; nt < 16; nt++)
#pragma unroll
        for (int e = 0; e < 4; e++) oacc[nt][e] = 0.0f;

    const int rq = lane >> 2;
    const int cq = (lane & 3) * 2;
    const float s2scale = SCALE * LOG2E;

    for (int jt = 0; jt <= jlast; jt++) {
        if (jt + 1 <= jlast) { load_stage((jt + 1) & 1, jt + 1); CP_COMMIT(); CP_WAIT(1); }
        else                 { CP_WAIT(0); }
        __syncthreads();

        const bool active = (jt * 64 <= qbase + wr + 15);
        if (active) {
            const uint32_t stage = sbase + FSTAGE0 + (jt & 1) * FSTAGE_B;

            float sacc[8][4];
#pragma unroll
            for (int nt = 0; nt < 8; nt++)
#pragma unroll
                for (int e = 0; e < 4; e++) sacc[nt][e] = 0.0f;

            const int arow = wr + (lane & 15);
            const int acol16 = (lane >> 4) * 16;
            const int bl8 = lane & 7;
            const int bsel = ((lane >> 3) & 1) * 16;

#pragma unroll
            for (int kk = 0; kk < 8; kk++) {
                uint32_t ah[4], al[4];
                uint32_t qaddr = sbase + FQ_H + arow * FROW + kk * 32 + acol16;
                ldsm_x4(ah, qaddr);
                ldsm_x4(al, qaddr + FQ_L);
#pragma unroll
                for (int nt = 0; nt < 8; nt++) {
                    uint32_t bh[2], bl[2];
                    uint32_t kaddr = stage + FK_H + (nt * 8 + bl8) * FROW + kk * 32 + bsel;
                    ldsm_x2(bh, kaddr);
                    ldsm_x2(bl, kaddr + (FK_L - FK_H));
                    mma16816(sacc[nt], ah, bh);
                    mma16816(sacc[nt], ah, bl);
                    mma16816(sacc[nt], al, bh);
                }
            }

            const int row0 = qbase + wr + rq;
            if (jt >= 2 * qt) {
#pragma unroll
                for (int nt = 0; nt < 8; nt++) {
                    int col = jt * 64 + nt * 8 + cq;
#pragma unroll
                    for (int e = 0; e < 4; e++) {
                        int cc = col + (e & 1);
                        int rr = row0 + ((e >> 1) ? 8 : 0);
                        float sv = sacc[nt][e] * s2scale;
                        sacc[nt][e] = (cc > rr) ? -1e30f : sv;
                    }
                }
            } else {
#pragma unroll
                for (int nt = 0; nt < 8; nt++)
#pragma unroll
                    for (int e = 0; e < 4; e++) sacc[nt][e] *= s2scale;
            }

            float mx0 = -1e30f, mx1 = -1e30f;
#pragma unroll
            for (int nt = 0; nt < 8; nt++) {
                mx0 = fmaxf(mx0, fmaxf(sacc[nt][0], sacc[nt][1]));
                mx1 = fmaxf(mx1, fmaxf(sacc[nt][2], sacc[nt][3]));
            }
#pragma unroll
            for (int off = 1; off <= 2; off <<= 1) {
                mx0 = fmaxf(mx0, __shfl_xor_sync(0xffffffffu, mx0, off));
                mx1 = fmaxf(mx1, __shfl_xor_sync(0xffffffffu, mx1, off));
            }
            float mn0 = fmaxf(m0, mx0), mn1 = fmaxf(m1, mx1);
            float alpha0 = fast_exp2(m0 - mn0), alpha1 = fast_exp2(m1 - mn1);

            float rs0 = 0.0f, rs1 = 0.0f;
#pragma unroll
            for (int nt = 0; nt < 8; nt++) {
                sacc[nt][0] = fast_exp2(sacc[nt][0] - mn0);
                sacc[nt][1] = fast_exp2(sacc[nt][1] - mn0);
                sacc[nt][2] = fast_exp2(sacc[nt][2] - mn1);
                sacc[nt][3] = fast_exp2(sacc[nt][3] - mn1);
                rs0 += sacc[nt][0] + sacc[nt][1];
                rs1 += sacc[nt][2] + sacc[nt][3];
            }
#pragma unroll
            for (int off = 1; off <= 2; off <<= 1) {
                rs0 += __shfl_xor_sync(0xffffffffu, rs0, off);
                rs1 += __shfl_xor_sync(0xffffffffu, rs1, off);
            }
            l0 = l0 * alpha0 + rs0;
            l1 = l1 * alpha1 + rs1;
            m0 = mn0; m1 = mn1;

#pragma unroll
            for (int nt = 0; nt < 16; nt++) {
                oacc[nt][0] *= alpha0; oacc[nt][1] *= alpha0;
                oacc[nt][2] *= alpha1; oacc[nt][3] *= alpha1;
            }

            uint32_t ph[4][4], pl[4][4];
#pragma unroll
            for (int kt = 0; kt < 4; kt++) {
                const float* pA = sacc[2 * kt];
                const float* pB = sacc[2 * kt + 1];
                uint32_t h0 = packh2(pA[0], pA[1]);
                uint32_t h1 = packh2(pA[2], pA[3]);
                uint32_t h2 = packh2(pB[0], pB[1]);
                uint32_t h3 = packh2(pB[2], pB[3]);
                ph[kt][0] = h0; ph[kt][1] = h1; ph[kt][2] = h2; ph[kt][3] = h3;
                __half2 hh0 = *reinterpret_cast<__half2*>(&h0);
                __half2 hh1 = *reinterpret_cast<__half2*>(&h1);
                __half2 hh2 = *reinterpret_cast<__half2*>(&h2);
                __half2 hh3 = *reinterpret_cast<__half2*>(&h3);
                pl[kt][0] = packh2(pA[0] - __low2float(hh0), pA[1] - __high2float(hh0));
                pl[kt][1] = packh2(pA[2] - __low2float(hh1), pA[3] - __high2float(hh1));
                pl[kt][2] = packh2(pB[0] - __low2float(hh2), pB[1] - __high2float(hh2));
                pl[kt][3] = packh2(pB[2] - __low2float(hh3), pB[3] - __high2float(hh3));
            }

            const int vl16 = lane & 15;
#pragma unroll
            for (int kt = 0; kt < 4; kt++) {
#pragma unroll
                for (int nt = 0; nt < 16; nt++) {
                    uint32_t vh[2], vl[2];
                    uint32_t vaddr = stage + FV_H + (kt * 16 + vl16) * FROW + nt * 16;
                    ldsm_x2_trans(vh, vaddr);
                    ldsm_x2_trans(vl, vaddr + (FV_L - FV_H));
                    mma16816(oacc[nt], ph[kt], vh);
                    mma16816(oacc[nt], ph[kt], vl);
                    mma16816(oacc[nt], pl[kt], vh);
                }
            }
        }
        __syncthreads();
    }

    const float inv0 = 1.0f / l0;
    const float inv1 = 1.0f / l1;
    const int row0 = qbase + wr + (lane >> 2);
    const int colb = h * HD + (lane & 3) * 2;
#pragma unroll
    for (int nt = 0; nt < 16; nt++) {
        int col = colb + nt * 8;
        *(uint32_t*)(g_ah + (size_t)row0 * HID + col) =
            packh2(oacc[nt][0] * inv0, oacc[nt][1] * inv0);
        *(uint32_t*)(g_ah + (size_t)(row0 + 8) * HID + col) =
            packh2(oacc[nt][2] * inv1, oacc[nt][3] * inv1);
    }
}

// ==========================================================================
// launch
// ==========================================================================
extern "C" void kernel_launch(void* const* d_in, const int* in_sizes, int n_in,
                              void* d_out, int out_size)
{
    const int*   positions = (const int*)d_in[0];
    const float* hidden    = (const float*)d_in[1];
    const float* w_qkv     = (const float*)d_in[2];
    const float* w_o       = (const float*)d_in[3];
    float*       out       = (float*)d_out;

    void *p_qkv, *p_ah, *p_wqh, *p_woh;
    cudaGetSymbolAddress(&p_qkv,  g_qkv);
    cudaGetSymbolAddress(&p_ah,   g_ah);
    cudaGetSymbolAddress(&p_wqh,  g_wqh);
    cudaGetSymbolAddress(&p_woh,  g_woh);
    float* qkv  = (float*)p_qkv;
    __half* ah  = (__half*)p_ah;
    __half* wqh = (__half*)p_wqh;
    __half* woh = (__half*)p_woh;

    cudaFuncSetAttribute(gemm_hmma_hi,
                         cudaFuncAttributeMaxDynamicSharedMemorySize, GEMM1_SMEM);
    cudaFuncSetAttribute(flash_hmma_kernel,
                         cudaFuncAttributeMaxDynamicSharedMemorySize, FLASH_SMEM);

    // 1) operand prep for QKV GEMM
    {
        int n4 = (S_LEN * HID) / 4;
        convert_hi<<<(n4 + 255) / 256, 256>>>(hidden, ah, n4);
        dim3 tg(QKV_N / 32, HID / 32);
        transpose_hi<<<tg, dim3(32, 8)>>>(w_qkv, wqh, HID, QKV_N);
    }
    // 2) QKV projection (1-term fp16)
    {
        dim3 grid(QKV_N / 128, S_LEN / 128);
        gemm_hmma_hi<<<grid, 256, GEMM1_SMEM>>>(ah, wqh, qkv, QKV_N, HID);
    }
    // 3) RoPE + fp16 hi/lo split (head-major)
    rope_split_kernel<<<S_LEN, 256>>>(positions);
    // 4) HMMA flash attention (full 3-term) -> writes attn hi into g_ah
    {
        dim3 grid(S_LEN / 128, NH);
        flash_hmma_kernel<<<grid, 256, FLASH_SMEM>>>();
    }
    // 5) O-GEMM weight prep
    {
        dim3 tg(HID / 32, QS / 32);
        transpose_hi<<<tg, dim3(32, 8)>>>(w_o, woh, QS, HID);
    }
    // 6) output projection (1-term fp16)
    {
        dim3 grid(HID / 128, S_LEN / 128);
        gemm_hmma_hi<<<grid, 256, GEMM1_SMEM>>>(ah, woh, out, HID, QS);
    }
}

// round 15
// speedup vs baseline: 1.2284x; 1.2284x over previous
#include <cuda_runtime.h>
#include <cuda_fp16.h>
#include <cstdint>
#include <math.h>

// ---------------- problem constants ----------------
#define S_LEN 2048
#define HID   4096
#define NH    32
#define NKV   8
#define HD    128
#define QS    (NH * HD)          // 4096
#define KVS   (NKV * HD)         // 1024
#define QKV_N (QS + 2 * KVS)     // 6144
#define SCALE 0.08838834764831845f  // 128^-0.5
#define LOG2E 1.4426950408889634f

// ---------------- scratch (static device globals; no allocs) ----------------
__device__ float g_qkv[S_LEN * QKV_N];       // QKV projection output [S, 6144]

// fp16 operands
__device__ __half g_ah[S_LEN * HID];         // activation hi [M,K] (hidden, then attn)
__device__ __half g_al[S_LEN * HID];         // activation lo (hidden only)
__device__ __half g_wqh[QKV_N * HID];        // w_qkv^T hi [N,K]
__device__ __half g_woh[HID * QS];           // w_o^T hi   [N,K]

// fp16 split Q/K/V, head-major [h][s][d] (flash keeps full precision)
__device__ __half g_qh[NH * S_LEN * HD];
__device__ __half g_ql[NH * S_LEN * HD];
__device__ __half g_kh[NKV * S_LEN * HD];
__device__ __half g_kl[NKV * S_LEN * HD];
__device__ __half g_vh[NKV * S_LEN * HD];
__device__ __half g_vl[NKV * S_LEN * HD];

// ==========================================================================
// small PTX helpers
// ==========================================================================
__device__ __forceinline__ uint32_t smem_to_u32(const void* p) {
    uint32_t a;
    asm("{ .reg .u64 t; cvta.to.shared.u64 t, %1; cvt.u32.u64 %0, t; }"
        : "=r"(a) : "l"(p));
    return a;
}
__device__ __forceinline__ void cp_async16(uint32_t dst, const void* src) {
    asm volatile("cp.async.cg.shared.global [%0], [%1], 16;"
                 :: "r"(dst), "l"(src) : "memory");
}
#define CP_COMMIT() asm volatile("cp.async.commit_group;" ::: "memory")
#define CP_WAIT(n)  asm volatile("cp.async.wait_group %0;" :: "n"(n) : "memory")

__device__ __forceinline__ void ldsm_x4(uint32_t* r, uint32_t addr) {
    asm volatile("ldmatrix.sync.aligned.m8n8.x4.shared.b16 {%0,%1,%2,%3}, [%4];"
                 : "=r"(r[0]), "=r"(r[1]), "=r"(r[2]), "=r"(r[3]) : "r"(addr));
}
__device__ __forceinline__ void ldsm_x2(uint32_t* r, uint32_t addr) {
    asm volatile("ldmatrix.sync.aligned.m8n8.x2.shared.b16 {%0,%1}, [%2];"
                 : "=r"(r[0]), "=r"(r[1]) : "r"(addr));
}
__device__ __forceinline__ void ldsm_x2_trans(uint32_t* r, uint32_t addr) {
    asm volatile("ldmatrix.sync.aligned.m8n8.x2.trans.shared.b16 {%0,%1}, [%2];"
                 : "=r"(r[0]), "=r"(r[1]) : "r"(addr));
}
__device__ __forceinline__ void mma16816(float* c, const uint32_t* a, const uint32_t* b) {
    asm volatile("mma.sync.aligned.m16n8k16.row.col.f32.f16.f16.f32 "
                 "{%0,%1,%2,%3}, {%4,%5,%6,%7}, {%8,%9}, {%0,%1,%2,%3};"
                 : "+f"(c[0]), "+f"(c[1]), "+f"(c[2]), "+f"(c[3])
                 : "r"(a[0]), "r"(a[1]), "r"(a[2]), "r"(a[3]),
                   "r"(b[0]), "r"(b[1]));
}
__device__ __forceinline__ uint32_t packh2(float a, float b) {
    __half2 h = __floats2half2_rn(a, b);
    return *reinterpret_cast<uint32_t*>(&h);
}
// fast 2^t on FMA/ALU pipes (avoids MUFU bottleneck); rel err ~1e-7
__device__ __forceinline__ float fast_exp2(float t) {
    t = fmaxf(t, -126.0f);
    float z = t + 12582912.0f;                       // round-to-nearest-int trick
    int   n = __float_as_int(z) - 0x4B400000;
    float f = t - (z - 12582912.0f);                 // f in [-0.5, 0.5]
    float p = 1.5435339e-4f;
    p = fmaf(p, f, 1.3333558e-3f);
    p = fmaf(p, f, 9.6181291e-3f);
    p = fmaf(p, f, 5.5504109e-2f);
    p = fmaf(p, f, 2.4022651e-1f);
    p = fmaf(p, f, 6.9314718e-1f);
    p = fmaf(p, f, 1.0f);
    return __int_as_float(__float_as_int(p) + (n << 23));
}

// BK=64 tiles: 128 rows x 64 fp16 (128B), padded row stride 144B.
// Row stride 144B = 36 words -> 8-row ldmatrix touches banks {0,4,...,28}: conflict-free.
#define ROW64_B  144
#define TILE64_B (128 * ROW64_B)        // 18432

// ==========================================================================
// 2-term split GEMM (QKV): C = (Ah+Al)[M,K] @ Bh[N,K]^T, BK=64.
// 8 warps, warp tile 64x32, 2-stage. Stage: Ah, Al, Bh (54KB) -> 2 CTAs/SM.
// ==========================================================================
#define STAGE2_B (3 * TILE64_B)          // 55296
#define GEMM2_SMEM (2 * STAGE2_B)        // 110592

__global__ __launch_bounds__(256) void gemm_hmma_split(
    const __half* __restrict__ Ah, const __half* __restrict__ Al,
    const __half* __restrict__ Bh,
    float* __restrict__ C, int Nglob, int Kglob)
{
    extern __shared__ __align__(128) char smem[];
    const uint32_t sbase = smem_to_u32(smem);
    const int tid  = threadIdx.x;
    const int wid  = tid >> 5;
    const int lane = tid & 31;
    const int brow = blockIdx.y * 128;
    const int bcol = blockIdx.x * 128;
    const int NC   = Kglob / 64;

    const int wm = (wid >> 2) * 64;
    const int wn = (wid & 3) * 32;

    const __half* __restrict__ srcs[3] = { Ah, Al, Bh };

    float acc[4][4][4];
#pragma unroll
    for (int i = 0; i < 4; i++)
#pragma unroll
        for (int j = 0; j < 4; j++)
#pragma unroll
            for (int e = 0; e < 4; e++) acc[i][j][e] = 0.0f;

    // stage loader: 3 tiles x 1024 chunks = 3072 / 256 thr = 12 each
    auto load_stage = [&](int s, int c) {
        const int k0 = c * 64;
        const uint32_t stage = sbase + s * STAGE2_B;
#pragma unroll
        for (int m = 0; m < 3; m++) {
            const int rowbase = (m < 2) ? brow : bcol;
            const __half* src = srcs[m];
#pragma unroll
            for (int t = 0; t < 4; t++) {
                int e  = tid + t * 256;       // 0..1023
                int r  = e >> 3;              // row 0..127
                int cc = e & 7;               // 16B chunk within row
                const void* g = src + (size_t)(rowbase + r) * Kglob + k0 + cc * 8;
                cp_async16(stage + m * TILE64_B + r * ROW64_B + cc * 16, g);
            }
        }
    };

    load_stage(0, 0);
    CP_COMMIT();

    for (int c = 0; c < NC; c++) {
        if (c + 1 < NC) { load_stage((c + 1) & 1, c + 1); CP_COMMIT(); CP_WAIT(1); }
        else            { CP_WAIT(0); }
        __syncthreads();

        const uint32_t st = sbase + (c & 1) * STAGE2_B;
        const uint32_t a_base = st;
        const uint32_t b_base = st + 2 * TILE64_B;

        const int arow = wm + (lane & 15);
        const int acol16 = (lane >> 4) * 16;
        const int brow8 = wn + (lane & 7);
        const int bcol16 = ((lane >> 3) & 1) * 16;

#pragma unroll
        for (int ks = 0; ks < 4; ks++) {
            const int koff = ks * 32;
            uint32_t ahf[4][4], alf[4][4], bhf[4][2];
#pragma unroll
            for (int i = 0; i < 4; i++) {
                uint32_t addr = a_base + (arow + i * 16) * ROW64_B + acol16 + koff;
                ldsm_x4(ahf[i], addr);
                ldsm_x4(alf[i], addr + TILE64_B);
            }
#pragma unroll
            for (int j = 0; j < 4; j++) {
                uint32_t addr = b_base + (brow8 + j * 8) * ROW64_B + bcol16 + koff;
                ldsm_x2(bhf[j], addr);
            }
#pragma unroll
            for (int i = 0; i < 4; i++)
#pragma unroll
                for (int j = 0; j < 4; j++) {
                    mma16816(acc[i][j], ahf[i], bhf[j]);
                    mma16816(acc[i][j], alf[i], bhf[j]);
                }
        }
        __syncthreads();
    }

    const int erow = brow + wm + (lane >> 2);
    const int ecol = bcol + wn + (lane & 3) * 2;
#pragma unroll
    for (int i = 0; i < 4; i++) {
#pragma unroll
        for (int j = 0; j < 4; j++) {
            float* p0 = C + (size_t)(erow + i * 16) * Nglob + ecol + j * 8;
            float* p1 = C + (size_t)(erow + i * 16 + 8) * Nglob + ecol + j * 8;
            *(float2*)p0 = make_float2(acc[i][j][0], acc[i][j][1]);
            *(float2*)p1 = make_float2(acc[i][j][2], acc[i][j][3]);
        }
    }
}

// ==========================================================================
// 1-term fp16 GEMM (O-projection): C = Ah[M,K] @ Bh[N,K]^T, BK=64.
// Stage: Ah, Bh (36KB) -> 3 CTAs/SM possible.
// ==========================================================================
#define STAGE1_B (2 * TILE64_B)          // 36864
#define GEMM1_SMEM (2 * STAGE1_B)        // 73728

__global__ __launch_bounds__(256) void gemm_hmma_hi(
    const __half* __restrict__ Ah, const __half* __restrict__ Bh,
    float* __restrict__ C, int Nglob, int Kglob)
{
    extern __shared__ __align__(128) char smem[];
    const uint32_t sbase = smem_to_u32(smem);
    const int tid  = threadIdx.x;
    const int wid  = tid >> 5;
    const int lane = tid & 31;
    const int brow = blockIdx.y * 128;
    const int bcol = blockIdx.x * 128;
    const int NC   = Kglob / 64;

    const int wm = (wid >> 2) * 64;
    const int wn = (wid & 3) * 32;

    const __half* __restrict__ srcs[2] = { Ah, Bh };

    float acc[4][4][4];
#pragma unroll
    for (int i = 0; i < 4; i++)
#pragma unroll
        for (int j = 0; j < 4; j++)
#pragma unroll
            for (int e = 0; e < 4; e++) acc[i][j][e] = 0.0f;

    // stage loader: 2 tiles x 1024 chunks = 2048 / 256 thr = 8 each
    auto load_stage = [&](int s, int c) {
        const int k0 = c * 64;
        const uint32_t stage = sbase + s * STAGE1_B;
#pragma unroll
        for (int m = 0; m < 2; m++) {
            const int rowbase = (m < 1) ? brow : bcol;
            const __half* src = srcs[m];
#pragma unroll
            for (int t = 0; t < 4; t++) {
                int e  = tid + t * 256;
                int r  = e >> 3;
                int cc = e & 7;
                const void* g = src + (size_t)(rowbase + r) * Kglob + k0 + cc * 8;
                cp_async16(stage + m * TILE64_B + r * ROW64_B + cc * 16, g);
            }
        }
    };

    load_stage(0, 0);
    CP_COMMIT();

    for (int c = 0; c < NC; c++) {
        if (c + 1 < NC) { load_stage((c + 1) & 1, c + 1); CP_COMMIT(); CP_WAIT(1); }
        else            { CP_WAIT(0); }
        __syncthreads();

        const uint32_t st = sbase + (c & 1) * STAGE1_B;
        const uint32_t a_base = st;
        const uint32_t b_base = st + TILE64_B;

        const int arow = wm + (lane & 15);
        const int acol16 = (lane >> 4) * 16;
        const int brow8 = wn + (lane & 7);
        const int bcol16 = ((lane >> 3) & 1) * 16;

#pragma unroll
        for (int ks = 0; ks < 4; ks++) {
            const int koff = ks * 32;
            uint32_t ahf[4][4], bhf[4][2];
#pragma unroll
            for (int i = 0; i < 4; i++)
                ldsm_x4(ahf[i], a_base + (arow + i * 16) * ROW64_B + acol16 + koff);
#pragma unroll
            for (int j = 0; j < 4; j++)
                ldsm_x2(bhf[j], b_base + (brow8 + j * 8) * ROW64_B + bcol16 + koff);
#pragma unroll
            for (int i = 0; i < 4; i++)
#pragma unroll
                for (int j = 0; j < 4; j++)
                    mma16816(acc[i][j], ahf[i], bhf[j]);
        }
        __syncthreads();
    }

    const int erow = brow + wm + (lane >> 2);
    const int ecol = bcol + wn + (lane & 3) * 2;
#pragma unroll
    for (int i = 0; i < 4; i++) {
#pragma unroll
        for (int j = 0; j < 4; j++) {
            float* p0 = C + (size_t)(erow + i * 16) * Nglob + ecol + j * 8;
            float* p1 = C + (size_t)(erow + i * 16 + 8) * Nglob + ecol + j * 8;
            *(float2*)p0 = make_float2(acc[i][j][0], acc[i][j][1]);
            *(float2*)p1 = make_float2(acc[i][j][2], acc[i][j][3]);
        }
    }
}

// ==========================================================================
// fp32 -> fp16 hi/lo split
// ==========================================================================
__global__ __launch_bounds__(256) void convert_split(
    const float* __restrict__ x, __half* __restrict__ hi,
    __half* __restrict__ lo, int n4)
{
    int i = blockIdx.x * 256 + threadIdx.x;
    if (i >= n4) return;
    float4 v = ((const float4*)x)[i];
    float vals[4] = {v.x, v.y, v.z, v.w};
    __half hs[4], ls[4];
#pragma unroll
    for (int j = 0; j < 4; j++) {
        __half h = __float2half_rn(vals[j]);
        hs[j] = h;
        ls[j] = __float2half_rn(vals[j] - __half2float(h));
    }
    *(uint2*)(hi + i * 4) = *(uint2*)hs;
    *(uint2*)(lo + i * 4) = *(uint2*)ls;
}

// ==========================================================================
// W[K,N] fp32 -> W^T[N,K] fp16 (hi only)
// ==========================================================================
__global__ __launch_bounds__(256) void transpose_hi(
    const float* __restrict__ W, __half* __restrict__ th, int K, int N)
{
    __shared__ float t[32][33];
    const int bx = blockIdx.x * 32;
    const int by = blockIdx.y * 32;
    const int tx = threadIdx.x;
    const int ty = threadIdx.y;
#pragma unroll
    for (int i = 0; i < 32; i += 8)
        t[ty + i][tx] = W[(size_t)(by + ty + i) * N + bx + tx];
    __syncthreads();
#pragma unroll
    for (int i = 0; i < 32; i += 8) {
        float v = t[tx][ty + i];
        th[(size_t)(bx + ty + i) * K + by + tx] = __float2half_rn(v);
    }
}

// ==========================================================================
// RoPE + split -> fp16 hi/lo Q/K/V, head-major
// ==========================================================================
__global__ __launch_bounds__(256) void rope_split_kernel(const int* __restrict__ positions)
{
    const int s   = blockIdx.x;
    const int tid = threadIdx.x;
    __shared__ float cs[64], sn[64];

    if (tid < 64) {
        float inv_freq = powf(10000.0f, -((float)(2 * tid)) / 128.0f);
        float ang = (float)positions[s] * inv_freq;
        cs[tid] = cosf(ang);
        sn[tid] = sinf(ang);
    }
    __syncthreads();

    const float* row = g_qkv + (size_t)s * QKV_N;

    for (int idx = tid; idx < NH * 64; idx += 256) {
        int h = idx >> 6, d = idx & 63;
        float x1 = row[h * HD + d];
        float x2 = row[h * HD + d + 64];
        float a = x1 * cs[d] - x2 * sn[d];
        float b = x2 * cs[d] + x1 * sn[d];
        size_t o = ((size_t)h * S_LEN + s) * HD;
        __half ha = __float2half_rn(a), hb = __float2half_rn(b);
        g_qh[o + d]      = ha;
        g_qh[o + d + 64] = hb;
        g_ql[o + d]      = __float2half_rn(a - __half2float(ha));
        g_ql[o + d + 64] = __float2half_rn(b - __half2float(hb));
    }
    for (int idx = tid; idx < NKV * 64; idx += 256) {
        int h = idx >> 6, d = idx & 63;
        const float* kr = row + QS;
        float x1 = kr[h * HD + d];
        float x2 = kr[h * HD + d + 64];
        float a = x1 * cs[d] - x2 * sn[d];
        float b = x2 * cs[d] + x1 * sn[d];
        size_t o = ((size_t)h * S_LEN + s) * HD;
        __half ha = __float2half_rn(a), hb = __float2half_rn(b);
        g_kh[o + d]      = ha;
        g_kh[o + d + 64] = hb;
        g_kl[o + d]      = __float2half_rn(a - __half2float(ha));
        g_kl[o + d + 64] = __float2half_rn(b - __half2float(hb));
    }
    for (int idx = tid; idx < NKV * HD; idx += 256) {
        int h = idx >> 7, d = idx & 127;
        float v = row[QS + KVS + h * HD + d];
        size_t o = ((size_t)h * S_LEN + s) * HD + d;
        __half hv = __float2half_rn(v);
        g_vh[o] = hv;
        g_vl[o] = __float2half_rn(v - __half2float(hv));
    }
}

// ==========================================================================
// HMMA flash attention: BR=128, BC=64, 8 warps, causal GQA.
// Full 3-term split math (error reserve). Heaviest q-tiles first.
// Epilogue writes attn hi into g_ah for the 1-term O-GEMM.
// ==========================================================================
#define FROW 272
#define FQ_H 0
#define FQ_L (128 * FROW)
#define FSTAGE0 (2 * 128 * FROW)
#define FSTAGE_B (4 * 64 * FROW)
#define FK_H 0
#define FK_L (64 * FROW)
#define FV_H (2 * 64 * FROW)
#define FV_L (3 * 64 * FROW)
#define FLASH_SMEM (FSTAGE0 + 2 * FSTAGE_B)

__global__ __launch_bounds__(256, 1) void flash_hmma_kernel()
{
    extern __shared__ __align__(128) char smem[];
    const uint32_t sbase = smem_to_u32(smem);
    const int tid  = threadIdx.x;
    const int wid  = tid >> 5;
    const int lane = tid & 31;
    const int qt   = gridDim.x - 1 - blockIdx.x;   // heavy tiles launch first
    const int h    = blockIdx.y;
    const int kvh  = h >> 2;
    const int qbase = qt * 128;
    const int wr   = wid * 16;
    const int jlast = 2 * qt + 1;

    const __half* Qhg = g_qh + ((size_t)h * S_LEN + qbase) * HD;
    const __half* Qlg = g_ql + ((size_t)h * S_LEN + qbase) * HD;
    const __half* Khg = g_kh + (size_t)kvh * S_LEN * HD;
    const __half* Klg = g_kl + (size_t)kvh * S_LEN * HD;
    const __half* Vhg = g_vh + (size_t)kvh * S_LEN * HD;
    const __half* Vlg = g_vl + (size_t)kvh * S_LEN * HD;

    {
#pragma unroll
        for (int t = 0; t < 8; t++) {
            int e = tid + t * 256;
            int r = e >> 4, c = e & 15;
            cp_async16(sbase + FQ_H + r * FROW + c * 16, Qhg + r * HD + c * 8);
        }
#pragma unroll
        for (int t = 0; t < 8; t++) {
            int e = tid + t * 256;
            int r = e >> 4, c = e & 15;
            cp_async16(sbase + FQ_L + r * FROW + c * 16, Qlg + r * HD + c * 8);
        }
    }

    auto load_stage = [&](int s, int jt) {
        const uint32_t stage = sbase + FSTAGE0 + s * FSTAGE_B;
        const int kbase = jt * 64;
        const __half* gs[4] = { Khg, Klg, Vhg, Vlg };
        const uint32_t off[4] = { FK_H, FK_L, FV_H, FV_L };
#pragma unroll
        for (int m = 0; m < 4; m++) {
#pragma unroll
            for (int t = 0; t < 4; t++) {
                int e = tid + t * 256;
                int r = e >> 4, c = e & 15;
                cp_async16(stage + off[m] + r * FROW + c * 16,
                           gs[m] + (size_t)(kbase + r) * HD + c * 8);
            }
        }
    };

    load_stage(0, 0);
    CP_COMMIT();

    float oacc[16][4];
    float m0 = -1e30f, m1 = -1e30f, l0 = 0.0f, l1 = 0.0f;
#pragma unroll
    for (int nt = 0; nt < 16; nt++)
#pragma unroll
        for (int e = 0; e < 4; e++) oacc[nt][e] = 0.0f;

    const int rq = lane >> 2;
    const int cq = (lane & 3) * 2;
    const float s2scale = SCALE * LOG2E;

    for (int jt = 0; jt <= jlast; jt++) {
        if (jt + 1 <= jlast) { load_stage((jt + 1) & 1, jt + 1); CP_COMMIT(); CP_WAIT(1); }
        else                 { CP_WAIT(0); }
        __syncthreads();

        const bool active = (jt * 64 <= qbase + wr + 15);
        if (active) {
            const uint32_t stage = sbase + FSTAGE0 + (jt & 1) * FSTAGE_B;

            float sacc[8][4];
#pragma unroll
            for (int nt = 0; nt < 8; nt++)
#pragma unroll
                for (int e = 0; e < 4; e++) sacc[nt][e] = 0.0f;

            const int arow = wr + (lane & 15);
            const int acol16 = (lane >> 4) * 16;
            const int bl8 = lane & 7;
            const int bsel = ((lane >> 3) & 1) * 16;

#pragma unroll
            for (int kk = 0; kk < 8; kk++) {
                uint32_t ah[4], al[4];
                uint32_t qaddr = sbase + FQ_H + arow * FROW + kk * 32 + acol16;
                ldsm_x4(ah, qaddr);
                ldsm_x4(al, qaddr + FQ_L);
#pragma unroll
                for (int nt = 0; nt < 8; nt++) {
                    uint32_t bh[2], bl[2];
                    uint32_t kaddr = stage + FK_H + (nt * 8 + bl8) * FROW + kk * 32 + bsel;
                    ldsm_x2(bh, kaddr);
                    ldsm_x2(bl, kaddr + (FK_L - FK_H));
                    mma16816(sacc[nt], ah, bh);
                    mma16816(sacc[nt], ah, bl);
                    mma16816(sacc[nt], al, bh);
                }
            }

            const int row0 = qbase + wr + rq;
            if (jt >= 2 * qt) {
#pragma unroll
                for (int nt = 0; nt < 8; nt++) {
                    int col = jt * 64 + nt * 8 + cq;
#pragma unroll
                    for (int e = 0; e < 4; e++) {
                        int cc = col + (e & 1);
                        int rr = row0 + ((e >> 1) ? 8 : 0);
                        float sv = sacc[nt][e] * s2scale;
                        sacc[nt][e] = (cc > rr) ? -1e30f : sv;
                    }
                }
            } else {
#pragma unroll
                for (int nt = 0; nt < 8; nt++)
#pragma unroll
                    for (int e = 0; e < 4; e++) sacc[nt][e] *= s2scale;
            }

            float mx0 = -1e30f, mx1 = -1e30f;
#pragma unroll
            for (int nt = 0; nt < 8; nt++) {
                mx0 = fmaxf(mx0, fmaxf(sacc[nt][0], sacc[nt][1]));
                mx1 = fmaxf(mx1, fmaxf(sacc[nt][2], sacc[nt][3]));
            }
#pragma unroll
            for (int off = 1; off <= 2; off <<= 1) {
                mx0 = fmaxf(mx0, __shfl_xor_sync(0xffffffffu, mx0, off));
                mx1 = fmaxf(mx1, __shfl_xor_sync(0xffffffffu, mx1, off));
            }
            float mn0 = fmaxf(m0, mx0), mn1 = fmaxf(m1, mx1);
            float alpha0 = fast_exp2(m0 - mn0), alpha1 = fast_exp2(m1 - mn1);

            float rs0 = 0.0f, rs1 = 0.0f;
#pragma unroll
            for (int nt = 0; nt < 8; nt++) {
                sacc[nt][0] = fast_exp2(sacc[nt][0] - mn0);
                sacc[nt][1] = fast_exp2(sacc[nt][1] - mn0);
                sacc[nt][2] = fast_exp2(sacc[nt][2] - mn1);
                sacc[nt][3] = fast_exp2(sacc[nt][3] - mn1);
                rs0 += sacc[nt][0] + sacc[nt][1];
                rs1 += sacc[nt][2] + sacc[nt][3];
            }
#pragma unroll
            for (int off = 1; off <= 2; off <<= 1) {
                rs0 += __shfl_xor_sync(0xffffffffu, rs0, off);
                rs1 += __shfl_xor_sync(0xffffffffu, rs1, off);
            }
            l0 = l0 * alpha0 + rs0;
            l1 = l1 * alpha1 + rs1;
            m0 = mn0; m1 = mn1;

#pragma unroll
            for (int nt = 0; nt < 16; nt++) {
                oacc[nt][0] *= alpha0; oacc[nt][1] *= alpha0;
                oacc[nt][2] *= alpha1; oacc[nt][3] *= alpha1;
            }

            uint32_t ph[4][4], pl[4][4];
#pragma unroll
            for (int kt = 0; kt < 4; kt++) {
                const float* pA = sacc[2 * kt];
                const float* pB = sacc[2 * kt + 1];
                uint32_t h0 = packh2(pA[0], pA[1]);
                uint32_t h1 = packh2(pA[2], pA[3]);
                uint32_t h2 = packh2(pB[0], pB[1]);
                uint32_t h3 = packh2(pB[2], pB[3]);
                ph[kt][0] = h0; ph[kt][1] = h1; ph[kt][2] = h2; ph[kt][3] = h3;
                __half2 hh0 = *reinterpret_cast<__half2*>(&h0);
                __half2 hh1 = *reinterpret_cast<__half2*>(&h1);
                __half2 hh2 = *reinterpret_cast<__half2*>(&h2);
                __half2 hh3 = *reinterpret_cast<__half2*>(&h3);
                pl[kt][0] = packh2(pA[0] - __low2float(hh0), pA[1] - __high2float(hh0));
                pl[kt][1] = packh2(pA[2] - __low2float(hh1), pA[3] - __high2float(hh1));
                pl[kt][2] = packh2(pB[0] - __low2float(hh2), pB[1] - __high2float(hh2));
                pl[kt][3] = packh2(pB[2] - __low2float(hh3), pB[3] - __high2float(hh3));
            }

            const int vl16 = lane & 15;
#pragma unroll
            for (int kt = 0; kt < 4; kt++) {
#pragma unroll
                for (int nt = 0; nt < 16; nt++) {
                    uint32_t vh[2], vl[2];
                    uint32_t vaddr = stage + FV_H + (kt * 16 + vl16) * FROW + nt * 16;
                    ldsm_x2_trans(vh, vaddr);
                    ldsm_x2_trans(vl, vaddr + (FV_L - FV_H));
                    mma16816(oacc[nt], ph[kt], vh);
                    mma16816(oacc[nt], ph[kt], vl);
                    mma16816(oacc[nt], pl[kt], vh);
                }
            }
        }
        __syncthreads();
    }

    const float inv0 = 1.0f / l0;
    const float inv1 = 1.0f / l1;
    const int row0 = qbase + wr + (lane >> 2);
    const int colb = h * HD + (lane & 3) * 2;
#pragma unroll
    for (int nt = 0; nt < 16; nt++) {
        int col = colb + nt * 8;
        *(uint32_t*)(g_ah + (size_t)row0 * HID + col) =
            packh2(oacc[nt][0] * inv0, oacc[nt][1] * inv0);
        *(uint32_t*)(g_ah + (size_t)(row0 + 8) * HID + col) =
            packh2(oacc[nt][2] * inv1, oacc[nt][3] * inv1);
    }
}

// ==========================================================================
// launch
// ==========================================================================
extern "C" void kernel_launch(void* const* d_in, const int* in_sizes, int n_in,
                              void* d_out, int out_size)
{
    const int*   positions = (const int*)d_in[0];
    const float* hidden    = (const float*)d_in[1];
    const float* w_qkv     = (const float*)d_in[2];
    const float* w_o       = (const float*)d_in[3];
    float*       out       = (float*)d_out;

    void *p_qkv, *p_ah, *p_al, *p_wqh, *p_woh;
    cudaGetSymbolAddress(&p_qkv,  g_qkv);
    cudaGetSymbolAddress(&p_ah,   g_ah);
    cudaGetSymbolAddress(&p_al,   g_al);
    cudaGetSymbolAddress(&p_wqh,  g_wqh);
    cudaGetSymbolAddress(&p_woh,  g_woh);
    float* qkv  = (float*)p_qkv;
    __half* ah  = (__half*)p_ah;
    __half* al  = (__half*)p_al;
    __half* wqh = (__half*)p_wqh;
    __half* woh = (__half*)p_woh;

    cudaFuncSetAttribute(gemm_hmma_split,
                         cudaFuncAttributeMaxDynamicSharedMemorySize, GEMM2_SMEM);
    cudaFuncSetAttribute(gemm_hmma_hi,
                         cudaFuncAttributeMaxDynamicSharedMemorySize, GEMM1_SMEM);
    cudaFuncSetAttribute(flash_hmma_kernel,
                         cudaFuncAttributeMaxDynamicSharedMemorySize, FLASH_SMEM);

    // 1) operand prep for QKV GEMM
    {
        int n4 = (S_LEN * HID) / 4;
        convert_split<<<(n4 + 255) / 256, 256>>>(hidden, ah, al, n4);
        dim3 tg(QKV_N / 32, HID / 32);
        transpose_hi<<<tg, dim3(32, 8)>>>(w_qkv, wqh, HID, QKV_N);
    }
    // 2) QKV projection (2-term split, BK=64)
    {
        dim3 grid(QKV_N / 128, S_LEN / 128);
        gemm_hmma_split<<<grid, 256, GEMM2_SMEM>>>(ah, al, wqh, qkv, QKV_N, HID);
    }
    // 3) RoPE + fp16 hi/lo split (head-major)
    rope_split_kernel<<<S_LEN, 256>>>(positions);
    // 4) HMMA flash attention (full 3-term) -> writes attn hi into g_ah
    {
        dim3 grid(S_LEN / 128, NH);
        flash_hmma_kernel<<<grid, 256, FLASH_SMEM>>>();
    }
    // 5) O-GEMM weight prep
    {
        dim3 tg(HID / 32, QS / 32);
        transpose_hi<<<tg, dim3(32, 8)>>>(w_o, woh, QS, HID);
    }
    // 6) output projection (1-term fp16, BK=64)
    {
        dim3 grid(HID / 128, S_LEN / 128);
        gemm_hmma_hi<<<grid, 256, GEMM1_SMEM>>>(ah, woh, out, HID, QS);
    }
}

// round 16
// speedup vs baseline: 1.3295x; 1.0823x over previous
#include <cuda_runtime.h>
#include <cuda_fp16.h>
#include <cstdint>
#include <math.h>

// ---------------- problem constants ----------------
#define S_LEN 2048
#define HID   4096
#define NH    32
#define NKV   8
#define HD    128
#define QS    (NH * HD)          // 4096
#define KVS   (NKV * HD)         // 1024
#define QKV_N (QS + 2 * KVS)     // 6144
#define SCALE 0.08838834764831845f  // 128^-0.5
#define LOG2E 1.4426950408889634f

// ---------------- scratch (static device globals; no allocs) ----------------
__device__ float g_qkv[S_LEN * QKV_N];       // QKV projection output [S, 6144]

// fp16 operands
__device__ __half g_ah[S_LEN * HID];         // activation hi [M,K] (hidden, then attn)
__device__ __half g_al[S_LEN * HID];         // activation lo (hidden only)
__device__ __half g_wqh[QKV_N * HID];        // w_qkv^T hi [N,K]
__device__ __half g_woh[HID * QS];           // w_o^T hi   [N,K]

// fp16 Q (hi/lo) and K/V (hi only), head-major [h][s][d]
__device__ __half g_qh[NH * S_LEN * HD];
__device__ __half g_ql[NH * S_LEN * HD];
__device__ __half g_kh[NKV * S_LEN * HD];
__device__ __half g_vh[NKV * S_LEN * HD];

// ==========================================================================
// small PTX helpers
// ==========================================================================
__device__ __forceinline__ uint32_t smem_to_u32(const void* p) {
    uint32_t a;
    asm("{ .reg .u64 t; cvta.to.shared.u64 t, %1; cvt.u32.u64 %0, t; }"
        : "=r"(a) : "l"(p));
    return a;
}
__device__ __forceinline__ void cp_async16(uint32_t dst, const void* src) {
    asm volatile("cp.async.cg.shared.global [%0], [%1], 16;"
                 :: "r"(dst), "l"(src) : "memory");
}
#define CP_COMMIT() asm volatile("cp.async.commit_group;" ::: "memory")
#define CP_WAIT(n)  asm volatile("cp.async.wait_group %0;" :: "n"(n) : "memory")

__device__ __forceinline__ void ldsm_x4(uint32_t* r, uint32_t addr) {
    asm volatile("ldmatrix.sync.aligned.m8n8.x4.shared.b16 {%0,%1,%2,%3}, [%4];"
                 : "=r"(r[0]), "=r"(r[1]), "=r"(r[2]), "=r"(r[3]) : "r"(addr));
}
__device__ __forceinline__ void ldsm_x2(uint32_t* r, uint32_t addr) {
    asm volatile("ldmatrix.sync.aligned.m8n8.x2.shared.b16 {%0,%1}, [%2];"
                 : "=r"(r[0]), "=r"(r[1]) : "r"(addr));
}
__device__ __forceinline__ void ldsm_x2_trans(uint32_t* r, uint32_t addr) {
    asm volatile("ldmatrix.sync.aligned.m8n8.x2.trans.shared.b16 {%0,%1}, [%2];"
                 : "=r"(r[0]), "=r"(r[1]) : "r"(addr));
}
__device__ __forceinline__ void mma16816(float* c, const uint32_t* a, const uint32_t* b) {
    asm volatile("mma.sync.aligned.m16n8k16.row.col.f32.f16.f16.f32 "
                 "{%0,%1,%2,%3}, {%4,%5,%6,%7}, {%8,%9}, {%0,%1,%2,%3};"
                 : "+f"(c[0]), "+f"(c[1]), "+f"(c[2]), "+f"(c[3])
                 : "r"(a[0]), "r"(a[1]), "r"(a[2]), "r"(a[3]),
                   "r"(b[0]), "r"(b[1]));
}
__device__ __forceinline__ uint32_t packh2(float a, float b) {
    __half2 h = __floats2half2_rn(a, b);
    return *reinterpret_cast<uint32_t*>(&h);
}
// fast 2^t on FMA/ALU pipes (avoids MUFU bottleneck); rel err ~1e-7
__device__ __forceinline__ float fast_exp2(float t) {
    t = fmaxf(t, -126.0f);
    float z = t + 12582912.0f;                       // round-to-nearest-int trick
    int   n = __float_as_int(z) - 0x4B400000;
    float f = t - (z - 12582912.0f);                 // f in [-0.5, 0.5]
    float p = 1.5435339e-4f;
    p = fmaf(p, f, 1.3333558e-3f);
    p = fmaf(p, f, 9.6181291e-3f);
    p = fmaf(p, f, 5.5504109e-2f);
    p = fmaf(p, f, 2.4022651e-1f);
    p = fmaf(p, f, 6.9314718e-1f);
    p = fmaf(p, f, 1.0f);
    return __int_as_float(__float_as_int(p) + (n << 23));
}

// BK=64 tiles: 128 rows x 64 fp16 (128B), padded row stride 144B.
#define ROW64_B  144
#define TILE64_B (128 * ROW64_B)        // 18432

// ==========================================================================
// 2-term split GEMM (QKV): C = (Ah+Al)[M,K] @ Bh[N,K]^T, BK=64.
// ==========================================================================
#define STAGE2_B (3 * TILE64_B)          // 55296
#define GEMM2_SMEM (2 * STAGE2_B)        // 110592

__global__ __launch_bounds__(256) void gemm_hmma_split(
    const __half* __restrict__ Ah, const __half* __restrict__ Al,
    const __half* __restrict__ Bh,
    float* __restrict__ C, int Nglob, int Kglob)
{
    extern __shared__ __align__(128) char smem[];
    const uint32_t sbase = smem_to_u32(smem);
    const int tid  = threadIdx.x;
    const int wid  = tid >> 5;
    const int lane = tid & 31;
    const int brow = blockIdx.y * 128;
    const int bcol = blockIdx.x * 128;
    const int NC   = Kglob / 64;

    const int wm = (wid >> 2) * 64;
    const int wn = (wid & 3) * 32;

    const __half* __restrict__ srcs[3] = { Ah, Al, Bh };

    float acc[4][4][4];
#pragma unroll
    for (int i = 0; i < 4; i++)
#pragma unroll
        for (int j = 0; j < 4; j++)
#pragma unroll
            for (int e = 0; e < 4; e++) acc[i][j][e] = 0.0f;

    auto load_stage = [&](int s, int c) {
        const int k0 = c * 64;
        const uint32_t stage = sbase + s * STAGE2_B;
#pragma unroll
        for (int m = 0; m < 3; m++) {
            const int rowbase = (m < 2) ? brow : bcol;
            const __half* src = srcs[m];
#pragma unroll
            for (int t = 0; t < 4; t++) {
                int e  = tid + t * 256;
                int r  = e >> 3;
                int cc = e & 7;
                const void* g = src + (size_t)(rowbase + r) * Kglob + k0 + cc * 8;
                cp_async16(stage + m * TILE64_B + r * ROW64_B + cc * 16, g);
            }
        }
    };

    load_stage(0, 0);
    CP_COMMIT();

    for (int c = 0; c < NC; c++) {
        if (c + 1 < NC) { load_stage((c + 1) & 1, c + 1); CP_COMMIT(); CP_WAIT(1); }
        else            { CP_WAIT(0); }
        __syncthreads();

        const uint32_t st = sbase + (c & 1) * STAGE2_B;
        const uint32_t a_base = st;
        const uint32_t b_base = st + 2 * TILE64_B;

        const int arow = wm + (lane & 15);
        const int acol16 = (lane >> 4) * 16;
        const int brow8 = wn + (lane & 7);
        const int bcol16 = ((lane >> 3) & 1) * 16;

#pragma unroll
        for (int ks = 0; ks < 4; ks++) {
            const int koff = ks * 32;
            uint32_t ahf[4][4], alf[4][4], bhf[4][2];
#pragma unroll
            for (int i = 0; i < 4; i++) {
                uint32_t addr = a_base + (arow + i * 16) * ROW64_B + acol16 + koff;
                ldsm_x4(ahf[i], addr);
                ldsm_x4(alf[i], addr + TILE64_B);
            }
#pragma unroll
            for (int j = 0; j < 4; j++) {
                uint32_t addr = b_base + (brow8 + j * 8) * ROW64_B + bcol16 + koff;
                ldsm_x2(bhf[j], addr);
            }
#pragma unroll
            for (int i = 0; i < 4; i++)
#pragma unroll
                for (int j = 0; j < 4; j++) {
                    mma16816(acc[i][j], ahf[i], bhf[j]);
                    mma16816(acc[i][j], alf[i], bhf[j]);
                }
        }
        __syncthreads();
    }

    const int erow = brow + wm + (lane >> 2);
    const int ecol = bcol + wn + (lane & 3) * 2;
#pragma unroll
    for (int i = 0; i < 4; i++) {
#pragma unroll
        for (int j = 0; j < 4; j++) {
            float* p0 = C + (size_t)(erow + i * 16) * Nglob + ecol + j * 8;
            float* p1 = C + (size_t)(erow + i * 16 + 8) * Nglob + ecol + j * 8;
            *(float2*)p0 = make_float2(acc[i][j][0], acc[i][j][1]);
            *(float2*)p1 = make_float2(acc[i][j][2], acc[i][j][3]);
        }
    }
}

// ==========================================================================
// 1-term fp16 GEMM (O-projection): C = Ah[M,K] @ Bh[N,K]^T, BK=64.
// ==========================================================================
#define STAGE1_B (2 * TILE64_B)          // 36864
#define GEMM1_SMEM (2 * STAGE1_B)        // 73728

__global__ __launch_bounds__(256) void gemm_hmma_hi(
    const __half* __restrict__ Ah, const __half* __restrict__ Bh,
    float* __restrict__ C, int Nglob, int Kglob)
{
    extern __shared__ __align__(128) char smem[];
    const uint32_t sbase = smem_to_u32(smem);
    const int tid  = threadIdx.x;
    const int wid  = tid >> 5;
    const int lane = tid & 31;
    const int brow = blockIdx.y * 128;
    const int bcol = blockIdx.x * 128;
    const int NC   = Kglob / 64;

    const int wm = (wid >> 2) * 64;
    const int wn = (wid & 3) * 32;

    const __half* __restrict__ srcs[2] = { Ah, Bh };

    float acc[4][4][4];
#pragma unroll
    for (int i = 0; i < 4; i++)
#pragma unroll
        for (int j = 0; j < 4; j++)
#pragma unroll
            for (int e = 0; e < 4; e++) acc[i][j][e] = 0.0f;

    auto load_stage = [&](int s, int c) {
        const int k0 = c * 64;
        const uint32_t stage = sbase + s * STAGE1_B;
#pragma unroll
        for (int m = 0; m < 2; m++) {
            const int rowbase = (m < 1) ? brow : bcol;
            const __half* src = srcs[m];
#pragma unroll
            for (int t = 0; t < 4; t++) {
                int e  = tid + t * 256;
                int r  = e >> 3;
                int cc = e & 7;
                const void* g = src + (size_t)(rowbase + r) * Kglob + k0 + cc * 8;
                cp_async16(stage + m * TILE64_B + r * ROW64_B + cc * 16, g);
            }
        }
    };

    load_stage(0, 0);
    CP_COMMIT();

    for (int c = 0; c < NC; c++) {
        if (c + 1 < NC) { load_stage((c + 1) & 1, c + 1); CP_COMMIT(); CP_WAIT(1); }
        else            { CP_WAIT(0); }
        __syncthreads();

        const uint32_t st = sbase + (c & 1) * STAGE1_B;
        const uint32_t a_base = st;
        const uint32_t b_base = st + TILE64_B;

        const int arow = wm + (lane & 15);
        const int acol16 = (lane >> 4) * 16;
        const int brow8 = wn + (lane & 7);
        const int bcol16 = ((lane >> 3) & 1) * 16;

#pragma unroll
        for (int ks = 0; ks < 4; ks++) {
            const int koff = ks * 32;
            uint32_t ahf[4][4], bhf[4][2];
#pragma unroll
            for (int i = 0; i < 4; i++)
                ldsm_x4(ahf[i], a_base + (arow + i * 16) * ROW64_B + acol16 + koff);
#pragma unroll
            for (int j = 0; j < 4; j++)
                ldsm_x2(bhf[j], b_base + (brow8 + j * 8) * ROW64_B + bcol16 + koff);
#pragma unroll
            for (int i = 0; i < 4; i++)
#pragma unroll
                for (int j = 0; j < 4; j++)
                    mma16816(acc[i][j], ahf[i], bhf[j]);
        }
        __syncthreads();
    }

    const int erow = brow + wm + (lane >> 2);
    const int ecol = bcol + wn + (lane & 3) * 2;
#pragma unroll
    for (int i = 0; i < 4; i++) {
#pragma unroll
        for (int j = 0; j < 4; j++) {
            float* p0 = C + (size_t)(erow + i * 16) * Nglob + ecol + j * 8;
            float* p1 = C + (size_t)(erow + i * 16 + 8) * Nglob + ecol + j * 8;
            *(float2*)p0 = make_float2(acc[i][j][0], acc[i][j][1]);
            *(float2*)p1 = make_float2(acc[i][j][2], acc[i][j][3]);
        }
    }
}

// ==========================================================================
// fp32 -> fp16 hi/lo split
// ==========================================================================
__global__ __launch_bounds__(256) void convert_split(
    const float* __restrict__ x, __half* __restrict__ hi,
    __half* __restrict__ lo, int n4)
{
    int i = blockIdx.x * 256 + threadIdx.x;
    if (i >= n4) return;
    float4 v = ((const float4*)x)[i];
    float vals[4] = {v.x, v.y, v.z, v.w};
    __half hs[4], ls[4];
#pragma unroll
    for (int j = 0; j < 4; j++) {
        __half h = __float2half_rn(vals[j]);
        hs[j] = h;
        ls[j] = __float2half_rn(vals[j] - __half2float(h));
    }
    *(uint2*)(hi + i * 4) = *(uint2*)hs;
    *(uint2*)(lo + i * 4) = *(uint2*)ls;
}

// ==========================================================================
// W[K,N] fp32 -> W^T[N,K] fp16 (hi only)
// ==========================================================================
__global__ __launch_bounds__(256) void transpose_hi(
    const float* __restrict__ W, __half* __restrict__ th, int K, int N)
{
    __shared__ float t[32][33];
    const int bx = blockIdx.x * 32;
    const int by = blockIdx.y * 32;
    const int tx = threadIdx.x;
    const int ty = threadIdx.y;
#pragma unroll
    for (int i = 0; i < 32; i += 8)
        t[ty + i][tx] = W[(size_t)(by + ty + i) * N + bx + tx];
    __syncthreads();
#pragma unroll
    for (int i = 0; i < 32; i += 8) {
        float v = t[tx][ty + i];
        th[(size_t)(bx + ty + i) * K + by + tx] = __float2half_rn(v);
    }
}

// ==========================================================================
// RoPE + split: Q -> hi/lo, K/V -> hi only, head-major
// ==========================================================================
__global__ __launch_bounds__(256) void rope_split_kernel(const int* __restrict__ positions)
{
    const int s   = blockIdx.x;
    const int tid = threadIdx.x;
    __shared__ float cs[64], sn[64];

    if (tid < 64) {
        float inv_freq = powf(10000.0f, -((float)(2 * tid)) / 128.0f);
        float ang = (float)positions[s] * inv_freq;
        cs[tid] = cosf(ang);
        sn[tid] = sinf(ang);
    }
    __syncthreads();

    const float* row = g_qkv + (size_t)s * QKV_N;

    for (int idx = tid; idx < NH * 64; idx += 256) {
        int h = idx >> 6, d = idx & 63;
        float x1 = row[h * HD + d];
        float x2 = row[h * HD + d + 64];
        float a = x1 * cs[d] - x2 * sn[d];
        float b = x2 * cs[d] + x1 * sn[d];
        size_t o = ((size_t)h * S_LEN + s) * HD;
        __half ha = __float2half_rn(a), hb = __float2half_rn(b);
        g_qh[o + d]      = ha;
        g_qh[o + d + 64] = hb;
        g_ql[o + d]      = __float2half_rn(a - __half2float(ha));
        g_ql[o + d + 64] = __float2half_rn(b - __half2float(hb));
    }
    for (int idx = tid; idx < NKV * 64; idx += 256) {
        int h = idx >> 6, d = idx & 63;
        const float* kr = row + QS;
        float x1 = kr[h * HD + d];
        float x2 = kr[h * HD + d + 64];
        float a = x1 * cs[d] - x2 * sn[d];
        float b = x2 * cs[d] + x1 * sn[d];
        size_t o = ((size_t)h * S_LEN + s) * HD;
        g_kh[o + d]      = __float2half_rn(a);
        g_kh[o + d + 64] = __float2half_rn(b);
    }
    for (int idx = tid; idx < NKV * HD; idx += 256) {
        int h = idx >> 7, d = idx & 127;
        float v = row[QS + KVS + h * HD + d];
        g_vh[((size_t)h * S_LEN + s) * HD + d] = __float2half_rn(v);
    }
}

// ==========================================================================
// HMMA flash attention: BR=128, BC=64, 8 warps, causal GQA.
// QK = (Qh+Ql)·Kh (2 terms); PV = (Ph+Pl)·Vh (2 terms). K/V hi-only.
// Heaviest q-tiles first. Epilogue writes attn hi into g_ah.
// ==========================================================================
#define FROW 272
#define FQ_H 0
#define FQ_L (128 * FROW)
#define FSTAGE0 (2 * 128 * FROW)          // 69632
#define FSTAGE_B (2 * 64 * FROW)          // 34816 (Kh, Vh)
#define FK_H 0
#define FV_H (64 * FROW)
#define FLASH_SMEM (FSTAGE0 + 2 * FSTAGE_B)   // 139264

__global__ __launch_bounds__(256, 1) void flash_hmma_kernel()
{
    extern __shared__ __align__(128) char smem[];
    const uint32_t sbase = smem_to_u32(smem);
    const int tid  = threadIdx.x;
    const int wid  = tid >> 5;
    const int lane = tid & 31;
    const int qt   = gridDim.x - 1 - blockIdx.x;   // heavy tiles launch first
    const int h    = blockIdx.y;
    const int kvh  = h >> 2;
    const int qbase = qt * 128;
    const int wr   = wid * 16;
    const int jlast = 2 * qt + 1;

    const __half* Qhg = g_qh + ((size_t)h * S_LEN + qbase) * HD;
    const __half* Qlg = g_ql + ((size_t)h * S_LEN + qbase) * HD;
    const __half* Khg = g_kh + (size_t)kvh * S_LEN * HD;
    const __half* Vhg = g_vh + (size_t)kvh * S_LEN * HD;

    {
#pragma unroll
        for (int t = 0; t < 8; t++) {
            int e = tid + t * 256;
            int r = e >> 4, c = e & 15;
            cp_async16(sbase + FQ_H + r * FROW + c * 16, Qhg + r * HD + c * 8);
        }
#pragma unroll
        for (int t = 0; t < 8; t++) {
            int e = tid + t * 256;
            int r = e >> 4, c = e & 15;
            cp_async16(sbase + FQ_L + r * FROW + c * 16, Qlg + r * HD + c * 8);
        }
    }

    auto load_stage = [&](int s, int jt) {
        const uint32_t stage = sbase + FSTAGE0 + s * FSTAGE_B;
        const int kbase = jt * 64;
        const __half* gs[2] = { Khg, Vhg };
        const uint32_t off[2] = { FK_H, FV_H };
#pragma unroll
        for (int m = 0; m < 2; m++) {
#pragma unroll
            for (int t = 0; t < 4; t++) {
                int e = tid + t * 256;
                int r = e >> 4, c = e & 15;
                cp_async16(stage + off[m] + r * FROW + c * 16,
                           gs[m] + (size_t)(kbase + r) * HD + c * 8);
            }
        }
    };

    load_stage(0, 0);
    CP_COMMIT();

    float oacc[16][4];
    float m0 = -1e30f, m1 = -1e30f, l0 = 0.0f, l1 = 0.0f;
#pragma unroll
    for (int nt = 0; nt < 16; nt++)
#pragma unroll
        for (int e = 0; e < 4; e++) oacc[nt][e] = 0.0f;

    const int rq = lane >> 2;
    const int cq = (lane & 3) * 2;
    const float s2scale = SCALE * LOG2E;

    for (int jt = 0; jt <= jlast; jt++) {
        if (jt + 1 <= jlast) { load_stage((jt + 1) & 1, jt + 1); CP_COMMIT(); CP_WAIT(1); }
        else                 { CP_WAIT(0); }
        __syncthreads();

        const bool active = (jt * 64 <= qbase + wr + 15);
        if (active) {
            const uint32_t stage = sbase + FSTAGE0 + (jt & 1) * FSTAGE_B;

            float sacc[8][4];
#pragma unroll
            for (int nt = 0; nt < 8; nt++)
#pragma unroll
                for (int e = 0; e < 4; e++) sacc[nt][e] = 0.0f;

            const int arow = wr + (lane & 15);
            const int acol16 = (lane >> 4) * 16;
            const int bl8 = lane & 7;
            const int bsel = ((lane >> 3) & 1) * 16;

#pragma unroll
            for (int kk = 0; kk < 8; kk++) {
                uint32_t ah[4], al[4];
                uint32_t qaddr = sbase + FQ_H + arow * FROW + kk * 32 + acol16;
                ldsm_x4(ah, qaddr);
                ldsm_x4(al, qaddr + FQ_L);
#pragma unroll
                for (int nt = 0; nt < 8; nt++) {
                    uint32_t bh[2];
                    uint32_t kaddr = stage + FK_H + (nt * 8 + bl8) * FROW + kk * 32 + bsel;
                    ldsm_x2(bh, kaddr);
                    mma16816(sacc[nt], ah, bh);
                    mma16816(sacc[nt], al, bh);
                }
            }

            const int row0 = qbase + wr + rq;
            if (jt >= 2 * qt) {
#pragma unroll
                for (int nt = 0; nt < 8; nt++) {
                    int col = jt * 64 + nt * 8 + cq;
#pragma unroll
                    for (int e = 0; e < 4; e++) {
                        int cc = col + (e & 1);
                        int rr = row0 + ((e >> 1) ? 8 : 0);
                        float sv = sacc[nt][e] * s2scale;
                        sacc[nt][e] = (cc > rr) ? -1e30f : sv;
                    }
                }
            } else {
#pragma unroll
                for (int nt = 0; nt < 8; nt++)
#pragma unroll
                    for (int e = 0; e < 4; e++) sacc[nt][e] *= s2scale;
            }

            float mx0 = -1e30f, mx1 = -1e30f;
#pragma unroll
            for (int nt = 0; nt < 8; nt++) {
                mx0 = fmaxf(mx0, fmaxf(sacc[nt][0], sacc[nt][1]));
                mx1 = fmaxf(mx1, fmaxf(sacc[nt][2], sacc[nt][3]));
            }
#pragma unroll
            for (int off = 1; off <= 2; off <<= 1) {
                mx0 = fmaxf(mx0, __shfl_xor_sync(0xffffffffu, mx0, off));
                mx1 = fmaxf(mx1, __shfl_xor_sync(0xffffffffu, mx1, off));
            }
            float mn0 = fmaxf(m0, mx0), mn1 = fmaxf(m1, mx1);
            float alpha0 = fast_exp2(m0 - mn0), alpha1 = fast_exp2(m1 - mn1);

            float rs0 = 0.0f, rs1 = 0.0f;
#pragma unroll
            for (int nt = 0; nt < 8; nt++) {
                sacc[nt][0] = fast_exp2(sacc[nt][0] - mn0);
                sacc[nt][1] = fast_exp2(sacc[nt][1] - mn0);
                sacc[nt][2] = fast_exp2(sacc[nt][2] - mn1);
                sacc[nt][3] = fast_exp2(sacc[nt][3] - mn1);
                rs0 += sacc[nt][0] + sacc[nt][1];
                rs1 += sacc[nt][2] + sacc[nt][3];
            }
#pragma unroll
            for (int off = 1; off <= 2; off <<= 1) {
                rs0 += __shfl_xor_sync(0xffffffffu, rs0, off);
                rs1 += __shfl_xor_sync(0xffffffffu, rs1, off);
            }
            l0 = l0 * alpha0 + rs0;
            l1 = l1 * alpha1 + rs1;
            m0 = mn0; m1 = mn1;

#pragma unroll
            for (int nt = 0; nt < 16; nt++) {
                oacc[nt][0] *= alpha0; oacc[nt][1] *= alpha0;
                oacc[nt][2] *= alpha1; oacc[nt][3] *= alpha1;
            }

            uint32_t ph[4][4], pl[4][4];
#pragma unroll
            for (int kt = 0; kt < 4; kt++) {
                const float* pA = sacc[2 * kt];
                const float* pB = sacc[2 * kt + 1];
                uint32_t h0 = packh2(pA[0], pA[1]);
                uint32_t h1 = packh2(pA[2], pA[3]);
                uint32_t h2 = packh2(pB[0], pB[1]);
                uint32_t h3 = packh2(pB[2], pB[3]);
                ph[kt][0] = h0; ph[kt][1] = h1; ph[kt][2] = h2; ph[kt][3] = h3;
                __half2 hh0 = *reinterpret_cast<__half2*>(&h0);
                __half2 hh1 = *reinterpret_cast<__half2*>(&h1);
                __half2 hh2 = *reinterpret_cast<__half2*>(&h2);
                __half2 hh3 = *reinterpret_cast<__half2*>(&h3);
                pl[kt][0] = packh2(pA[0] - __low2float(hh0), pA[1] - __high2float(hh0));
                pl[kt][1] = packh2(pA[2] - __low2float(hh1), pA[3] - __high2float(hh1));
                pl[kt][2] = packh2(pB[0] - __low2float(hh2), pB[1] - __high2float(hh2));
                pl[kt][3] = packh2(pB[2] - __low2float(hh3), pB[3] - __high2float(hh3));
            }

            const int vl16 = lane & 15;
#pragma unroll
            for (int kt = 0; kt < 4; kt++) {
#pragma unroll
                for (int nt = 0; nt < 16; nt++) {
                    uint32_t vh[2];
                    uint32_t vaddr = stage + FV_H + (kt * 16 + vl16) * FROW + nt * 16;
                    ldsm_x2_trans(vh, vaddr);
                    mma16816(oacc[nt], ph[kt], vh);
                    mma16816(oacc[nt], pl[kt], vh);
                }
            }
        }
        __syncthreads();
    }

    const float inv0 = 1.0f / l0;
    const float inv1 = 1.0f / l1;
    const int row0 = qbase + wr + (lane >> 2);
    const int colb = h * HD + (lane & 3) * 2;
#pragma unroll
    for (int nt = 0; nt < 16; nt++) {
        int col = colb + nt * 8;
        *(uint32_t*)(g_ah + (size_t)row0 * HID + col) =
            packh2(oacc[nt][0] * inv0, oacc[nt][1] * inv0);
        *(uint32_t*)(g_ah + (size_t)(row0 + 8) * HID + col) =
            packh2(oacc[nt][2] * inv1, oacc[nt][3] * inv1);
    }
}

// ==========================================================================
// launch
// ==========================================================================
extern "C" void kernel_launch(void* const* d_in, const int* in_sizes, int n_in,
                              void* d_out, int out_size)
{
    const int*   positions = (const int*)d_in[0];
    const float* hidden    = (const float*)d_in[1];
    const float* w_qkv     = (const float*)d_in[2];
    const float* w_o       = (const float*)d_in[3];
    float*       out       = (float*)d_out;

    void *p_qkv, *p_ah, *p_al, *p_wqh, *p_woh;
    cudaGetSymbolAddress(&p_qkv,  g_qkv);
    cudaGetSymbolAddress(&p_ah,   g_ah);
    cudaGetSymbolAddress(&p_al,   g_al);
    cudaGetSymbolAddress(&p_wqh,  g_wqh);
    cudaGetSymbolAddress(&p_woh,  g_woh);
    float* qkv  = (float*)p_qkv;
    __half* ah  = (__half*)p_ah;
    __half* al  = (__half*)p_al;
    __half* wqh = (__half*)p_wqh;
    __half* woh = (__half*)p_woh;

    cudaFuncSetAttribute(gemm_hmma_split,
                         cudaFuncAttributeMaxDynamicSharedMemorySize, GEMM2_SMEM);
    cudaFuncSetAttribute(gemm_hmma_hi,
                         cudaFuncAttributeMaxDynamicSharedMemorySize, GEMM1_SMEM);
    cudaFuncSetAttribute(flash_hmma_kernel,
                         cudaFuncAttributeMaxDynamicSharedMemorySize, FLASH_SMEM);

    // 1) operand prep for QKV GEMM
    {
        int n4 = (S_LEN * HID) / 4;
        convert_split<<<(n4 + 255) / 256, 256>>>(hidden, ah, al, n4);
        dim3 tg(QKV_N / 32, HID / 32);
        transpose_hi<<<tg, dim3(32, 8)>>>(w_qkv, wqh, HID, QKV_N);
    }
    // 2) QKV projection (2-term split, BK=64)
    {
        dim3 grid(QKV_N / 128, S_LEN / 128);
        gemm_hmma_split<<<grid, 256, GEMM2_SMEM>>>(ah, al, wqh, qkv, QKV_N, HID);
    }
    // 3) RoPE: Q hi/lo, K/V hi-only (head-major)
    rope_split_kernel<<<S_LEN, 256>>>(positions);
    // 4) HMMA flash attention (2-term QK, 2-term PV) -> writes attn hi into g_ah
    {
        dim3 grid(S_LEN / 128, NH);
        flash_hmma_kernel<<<grid, 256, FLASH_SMEM>>>();
    }
    // 5) O-GEMM weight prep
    {
        dim3 tg(HID / 32, QS / 32);
        transpose_hi<<<tg, dim3(32, 8)>>>(w_o, woh, QS, HID);
    }
    // 6) output projection (1-term fp16, BK=64)
    {
        dim3 grid(HID / 128, S_LEN / 128);
        gemm_hmma_hi<<<grid, 256, GEMM1_SMEM>>>(ah, woh, out, HID, QS);
    }
}

// round 17
// speedup vs baseline: 1.3990x; 1.0522x over previous
#include <cuda_runtime.h>
#include <cuda_fp16.h>
#include <cstdint>
#include <math.h>

// ---------------- problem constants ----------------
#define S_LEN 2048
#define HID   4096
#define NH    32
#define NKV   8
#define HD    128
#define QS    (NH * HD)          // 4096
#define KVS   (NKV * HD)         // 1024
#define QKV_N (QS + 2 * KVS)     // 6144
#define SCALE 0.08838834764831845f  // 128^-0.5
#define LOG2E 1.4426950408889634f

// ---------------- scratch (static device globals; no allocs) ----------------
// fp16 operands
__device__ __half g_ah[S_LEN * HID];         // activation hi [M,K] (hidden, then attn)
__device__ __half g_al[S_LEN * HID];         // activation lo (hidden only)
__device__ __half g_wqh[QKV_N * HID];        // w_qkv^T hi [N,K]
__device__ __half g_woh[HID * QS];           // w_o^T hi   [N,K]

// fp16 Q (hi/lo) and K/V (hi only), head-major [h][s][d]
__device__ __half g_qh[NH * S_LEN * HD];
__device__ __half g_ql[NH * S_LEN * HD];
__device__ __half g_kh[NKV * S_LEN * HD];
__device__ __half g_vh[NKV * S_LEN * HD];

// rope tables: cos/sin per (token, freq)
__device__ float g_cs[S_LEN * 64];
__device__ float g_sn[S_LEN * 64];

// ==========================================================================
// small PTX helpers
// ==========================================================================
__device__ __forceinline__ uint32_t smem_to_u32(const void* p) {
    uint32_t a;
    asm("{ .reg .u64 t; cvta.to.shared.u64 t, %1; cvt.u32.u64 %0, t; }"
        : "=r"(a) : "l"(p));
    return a;
}
__device__ __forceinline__ void cp_async16(uint32_t dst, const void* src) {
    asm volatile("cp.async.cg.shared.global [%0], [%1], 16;"
                 :: "r"(dst), "l"(src) : "memory");
}
#define CP_COMMIT() asm volatile("cp.async.commit_group;" ::: "memory")
#define CP_WAIT(n)  asm volatile("cp.async.wait_group %0;" :: "n"(n) : "memory")

__device__ __forceinline__ void ldsm_x4(uint32_t* r, uint32_t addr) {
    asm volatile("ldmatrix.sync.aligned.m8n8.x4.shared.b16 {%0,%1,%2,%3}, [%4];"
                 : "=r"(r[0]), "=r"(r[1]), "=r"(r[2]), "=r"(r[3]) : "r"(addr));
}
__device__ __forceinline__ void ldsm_x2(uint32_t* r, uint32_t addr) {
    asm volatile("ldmatrix.sync.aligned.m8n8.x2.shared.b16 {%0,%1}, [%2];"
                 : "=r"(r[0]), "=r"(r[1]) : "r"(addr));
}
__device__ __forceinline__ void ldsm_x2_trans(uint32_t* r, uint32_t addr) {
    asm volatile("ldmatrix.sync.aligned.m8n8.x2.trans.shared.b16 {%0,%1}, [%2];"
                 : "=r"(r[0]), "=r"(r[1]) : "r"(addr));
}
__device__ __forceinline__ void mma16816(float* c, const uint32_t* a, const uint32_t* b) {
    asm volatile("mma.sync.aligned.m16n8k16.row.col.f32.f16.f16.f32 "
                 "{%0,%1,%2,%3}, {%4,%5,%6,%7}, {%8,%9}, {%0,%1,%2,%3};"
                 : "+f"(c[0]), "+f"(c[1]), "+f"(c[2]), "+f"(c[3])
                 : "r"(a[0]), "r"(a[1]), "r"(a[2]), "r"(a[3]),
                   "r"(b[0]), "r"(b[1]));
}
__device__ __forceinline__ uint32_t packh2(float a, float b) {
    __half2 h = __floats2half2_rn(a, b);
    return *reinterpret_cast<uint32_t*>(&h);
}
// fast 2^t on FMA/ALU pipes (avoids MUFU bottleneck); rel err ~1e-7
__device__ __forceinline__ float fast_exp2(float t) {
    t = fmaxf(t, -126.0f);
    float z = t + 12582912.0f;                       // round-to-nearest-int trick
    int   n = __float_as_int(z) - 0x4B400000;
    float f = t - (z - 12582912.0f);                 // f in [-0.5, 0.5]
    float p = 1.5435339e-4f;
    p = fmaf(p, f, 1.3333558e-3f);
    p = fmaf(p, f, 9.6181291e-3f);
    p = fmaf(p, f, 5.5504109e-2f);
    p = fmaf(p, f, 2.4022651e-1f);
    p = fmaf(p, f, 6.9314718e-1f);
    p = fmaf(p, f, 1.0f);
    return __int_as_float(__float_as_int(p) + (n << 23));
}

// BK=64 tiles: 128 rows x 64 fp16 (128B), padded row stride 144B.
#define ROW64_B  144
#define TILE64_B (128 * ROW64_B)        // 18432

// epilogue staging: fp32 [128][133] (stride 133 -> conflict-light)
#define CS_STRIDE 133

// ==========================================================================
// Fused QKV GEMM + RoPE:
//   P = (Ah+Al)[M,K] @ Bh[N,K]^T (2-term split, BK=64),
//   then per-CTA epilogue applies NeoX rope (Q,K) / copy (V) and writes
//   fp16 head-major Q(hi/lo), K(hi), V(hi) directly. No fp32 intermediate.
// CTA tile 128x128 = (128 tokens) x (1 head). 8 warps, warp tile 64x32.
// ==========================================================================
#define STAGE2_B (3 * TILE64_B)          // 55296
#define GEMM2_SMEM (2 * STAGE2_B)        // 110592 (>= 128*133*4 = 68096 for epilogue)

__global__ __launch_bounds__(256) void gemm_qkv_rope(
    const __half* __restrict__ Ah, const __half* __restrict__ Al,
    const __half* __restrict__ Bh, int Kglob)
{
    extern __shared__ __align__(128) char smem[];
    const uint32_t sbase = smem_to_u32(smem);
    const int tid  = threadIdx.x;
    const int wid  = tid >> 5;
    const int lane = tid & 31;
    const int brow = blockIdx.y * 128;
    const int bcol = blockIdx.x * 128;
    const int NC   = Kglob / 64;

    const int wm = (wid >> 2) * 64;
    const int wn = (wid & 3) * 32;

    const __half* __restrict__ srcs[3] = { Ah, Al, Bh };

    float acc[4][4][4];
#pragma unroll
    for (int i = 0; i < 4; i++)
#pragma unroll
        for (int j = 0; j < 4; j++)
#pragma unroll
            for (int e = 0; e < 4; e++) acc[i][j][e] = 0.0f;

    auto load_stage = [&](int s, int c) {
        const int k0 = c * 64;
        const uint32_t stage = sbase + s * STAGE2_B;
#pragma unroll
        for (int m = 0; m < 3; m++) {
            const int rowbase = (m < 2) ? brow : bcol;
            const __half* src = srcs[m];
#pragma unroll
            for (int t = 0; t < 4; t++) {
                int e  = tid + t * 256;
                int r  = e >> 3;
                int cc = e & 7;
                const void* g = src + (size_t)(rowbase + r) * Kglob + k0 + cc * 8;
                cp_async16(stage + m * TILE64_B + r * ROW64_B + cc * 16, g);
            }
        }
    };

    load_stage(0, 0);
    CP_COMMIT();

    for (int c = 0; c < NC; c++) {
        if (c + 1 < NC) { load_stage((c + 1) & 1, c + 1); CP_COMMIT(); CP_WAIT(1); }
        else            { CP_WAIT(0); }
        __syncthreads();

        const uint32_t st = sbase + (c & 1) * STAGE2_B;
        const uint32_t a_base = st;
        const uint32_t b_base = st + 2 * TILE64_B;

        const int arow = wm + (lane & 15);
        const int acol16 = (lane >> 4) * 16;
        const int brow8 = wn + (lane & 7);
        const int bcol16 = ((lane >> 3) & 1) * 16;

#pragma unroll
        for (int ks = 0; ks < 4; ks++) {
            const int koff = ks * 32;
            uint32_t ahf[4][4], alf[4][4], bhf[4][2];
#pragma unroll
            for (int i = 0; i < 4; i++) {
                uint32_t addr = a_base + (arow + i * 16) * ROW64_B + acol16 + koff;
                ldsm_x4(ahf[i], addr);
                ldsm_x4(alf[i], addr + TILE64_B);
            }
#pragma unroll
            for (int j = 0; j < 4; j++) {
                uint32_t addr = b_base + (brow8 + j * 8) * ROW64_B + bcol16 + koff;
                ldsm_x2(bhf[j], addr);
            }
#pragma unroll
            for (int i = 0; i < 4; i++)
#pragma unroll
                for (int j = 0; j < 4; j++) {
                    mma16816(acc[i][j], ahf[i], bhf[j]);
                    mma16816(acc[i][j], alf[i], bhf[j]);
                }
        }
        __syncthreads();
    }

    // ---- stage fp32 tile to smem (mainloop buffers are dead past last sync)
    {
        float* csm = (float*)smem;
        const int er = wm + (lane >> 2);
        const int ec = wn + (lane & 3) * 2;
#pragma unroll
        for (int i = 0; i < 4; i++)
#pragma unroll
            for (int j = 0; j < 4; j++) {
                float* p0 = &csm[(er + i * 16) * CS_STRIDE + ec + j * 8];
                float* p1 = &csm[(er + i * 16 + 8) * CS_STRIDE + ec + j * 8];
                p0[0] = acc[i][j][0]; p0[1] = acc[i][j][1];
                p1[0] = acc[i][j][2]; p1[1] = acc[i][j][3];
            }
    }
    __syncthreads();

    // ---- rope + split + store (thread: row r = tid/2, freq half d0 = (tid&1)*32)
    {
        const float* csm = (const float*)smem;
        const int r  = tid >> 1;
        const int s  = brow + r;
        const int d0 = (tid & 1) * 32;
        const float* crow = csm + r * CS_STRIDE;

        if (bcol < QS) {                       // ---- Q: rope, hi + lo
            const int hh = bcol >> 7;
            __half* qh = g_qh + ((size_t)hh * S_LEN + s) * HD;
            __half* ql = g_ql + ((size_t)hh * S_LEN + s) * HD;
            const float* csr = g_cs + s * 64 + d0;
            const float* snr = g_sn + s * 64 + d0;
#pragma unroll
            for (int blk = 0; blk < 4; blk++) {
                uint32_t wa[4], wb[4], wla[4], wlb[4];
#pragma unroll
                for (int p = 0; p < 4; p++) {
                    int dd = blk * 8 + p * 2;
                    float x10 = crow[d0 + dd],      x11 = crow[d0 + dd + 1];
                    float x20 = crow[d0 + dd + 64], x21 = crow[d0 + dd + 65];
                    float c0 = csr[dd],     s0v = snr[dd];
                    float c1 = csr[dd + 1], s1v = snr[dd + 1];
                    float a0 = x10 * c0 - x20 * s0v, b0 = x20 * c0 + x10 * s0v;
                    float a1 = x11 * c1 - x21 * s1v, b1 = x21 * c1 + x11 * s1v;
                    uint32_t ha = packh2(a0, a1), hb = packh2(b0, b1);
                    wa[p] = ha; wb[p] = hb;
                    __half2 h2a = *(__half2*)&ha, h2b = *(__half2*)&hb;
                    wla[p] = packh2(a0 - __low2float(h2a), a1 - __high2float(h2a));
                    wlb[p] = packh2(b0 - __low2float(h2b), b1 - __high2float(h2b));
                }
                *(uint4*)(qh + d0 + blk * 8)      = make_uint4(wa[0], wa[1], wa[2], wa[3]);
                *(uint4*)(qh + d0 + blk * 8 + 64) = make_uint4(wb[0], wb[1], wb[2], wb[3]);
                *(uint4*)(ql + d0 + blk * 8)      = make_uint4(wla[0], wla[1], wla[2], wla[3]);
                *(uint4*)(ql + d0 + blk * 8 + 64) = make_uint4(wlb[0], wlb[1], wlb[2], wlb[3]);
            }
        } else if (bcol < QS + KVS) {          // ---- K: rope, hi only
            const int kvh = (bcol - QS) >> 7;
            __half* kh = g_kh + ((size_t)kvh * S_LEN + s) * HD;
            const float* csr = g_cs + s * 64 + d0;
            const float* snr = g_sn + s * 64 + d0;
#pragma unroll
            for (int blk = 0; blk < 4; blk++) {
                uint32_t wa[4], wb[4];
#pragma unroll
                for (int p = 0; p < 4; p++) {
                    int dd = blk * 8 + p * 2;
                    float x10 = crow[d0 + dd],      x11 = crow[d0 + dd + 1];
                    float x20 = crow[d0 + dd + 64], x21 = crow[d0 + dd + 65];
                    float c0 = csr[dd],     s0v = snr[dd];
                    float c1 = csr[dd + 1], s1v = snr[dd + 1];
                    float a0 = x10 * c0 - x20 * s0v, b0 = x20 * c0 + x10 * s0v;
                    float a1 = x11 * c1 - x21 * s1v, b1 = x21 * c1 + x11 * s1v;
                    wa[p] = packh2(a0, a1);
                    wb[p] = packh2(b0, b1);
                }
                *(uint4*)(kh + d0 + blk * 8)      = make_uint4(wa[0], wa[1], wa[2], wa[3]);
                *(uint4*)(kh + d0 + blk * 8 + 64) = make_uint4(wb[0], wb[1], wb[2], wb[3]);
            }
        } else {                               // ---- V: copy, hi only
            const int kvh = (bcol - QS - KVS) >> 7;
            __half* vh = g_vh + ((size_t)kvh * S_LEN + s) * HD;
#pragma unroll
            for (int blk = 0; blk < 4; blk++) {
                uint32_t wa[4], wb[4];
#pragma unroll
                for (int p = 0; p < 4; p++) {
                    int dd = blk * 8 + p * 2;
                    wa[p] = packh2(crow[d0 + dd],      crow[d0 + dd + 1]);
                    wb[p] = packh2(crow[d0 + dd + 64], crow[d0 + dd + 65]);
                }
                *(uint4*)(vh + d0 + blk * 8)      = make_uint4(wa[0], wa[1], wa[2], wa[3]);
                *(uint4*)(vh + d0 + blk * 8 + 64) = make_uint4(wb[0], wb[1], wb[2], wb[3]);
            }
        }
    }
}

// ==========================================================================
// rope table: cos/sin per (token, freq) — identical math to old rope kernel
// ==========================================================================
__global__ __launch_bounds__(256) void rope_table(const int* __restrict__ positions)
{
    int idx = blockIdx.x * 256 + threadIdx.x;
    if (idx >= S_LEN * 64) return;
    int s = idx >> 6, f = idx & 63;
    float inv_freq = powf(10000.0f, -((float)(2 * f)) / 128.0f);
    float ang = (float)positions[s] * inv_freq;
    g_cs[idx] = cosf(ang);
    g_sn[idx] = sinf(ang);
}

// ==========================================================================
// 1-term fp16 GEMM (O-projection): C = Ah[M,K] @ Bh[N,K]^T, BK=64.
// ==========================================================================
#define STAGE1_B (2 * TILE64_B)          // 36864
#define GEMM1_SMEM (2 * STAGE1_B)        // 73728

__global__ __launch_bounds__(256) void gemm_hmma_hi(
    const __half* __restrict__ Ah, const __half* __restrict__ Bh,
    float* __restrict__ C, int Nglob, int Kglob)
{
    extern __shared__ __align__(128) char smem[];
    const uint32_t sbase = smem_to_u32(smem);
    const int tid  = threadIdx.x;
    const int wid  = tid >> 5;
    const int lane = tid & 31;
    const int brow = blockIdx.y * 128;
    const int bcol = blockIdx.x * 128;
    const int NC   = Kglob / 64;

    const int wm = (wid >> 2) * 64;
    const int wn = (wid & 3) * 32;

    const __half* __restrict__ srcs[2] = { Ah, Bh };

    float acc[4][4][4];
#pragma unroll
    for (int i = 0; i < 4; i++)
#pragma unroll
        for (int j = 0; j < 4; j++)
#pragma unroll
            for (int e = 0; e < 4; e++) acc[i][j][e] = 0.0f;

    auto load_stage = [&](int s, int c) {
        const int k0 = c * 64;
        const uint32_t stage = sbase + s * STAGE1_B;
#pragma unroll
        for (int m = 0; m < 2; m++) {
            const int rowbase = (m < 1) ? brow : bcol;
            const __half* src = srcs[m];
#pragma unroll
            for (int t = 0; t < 4; t++) {
                int e  = tid + t * 256;
                int r  = e >> 3;
                int cc = e & 7;
                const void* g = src + (size_t)(rowbase + r) * Kglob + k0 + cc * 8;
                cp_async16(stage + m * TILE64_B + r * ROW64_B + cc * 16, g);
            }
        }
    };

    load_stage(0, 0);
    CP_COMMIT();

    for (int c = 0; c < NC; c++) {
        if (c + 1 < NC) { load_stage((c + 1) & 1, c + 1); CP_COMMIT(); CP_WAIT(1); }
        else            { CP_WAIT(0); }
        __syncthreads();

        const uint32_t st = sbase + (c & 1) * STAGE1_B;
        const uint32_t a_base = st;
        const uint32_t b_base = st + TILE64_B;

        const int arow = wm + (lane & 15);
        const int acol16 = (lane >> 4) * 16;
        const int brow8 = wn + (lane & 7);
        const int bcol16 = ((lane >> 3) & 1) * 16;

#pragma unroll
        for (int ks = 0; ks < 4; ks++) {
            const int koff = ks * 32;
            uint32_t ahf[4][4], bhf[4][2];
#pragma unroll
            for (int i = 0; i < 4; i++)
                ldsm_x4(ahf[i], a_base + (arow + i * 16) * ROW64_B + acol16 + koff);
#pragma unroll
            for (int j = 0; j < 4; j++)
                ldsm_x2(bhf[j], b_base + (brow8 + j * 8) * ROW64_B + bcol16 + koff);
#pragma unroll
            for (int i = 0; i < 4; i++)
#pragma unroll
                for (int j = 0; j < 4; j++)
                    mma16816(acc[i][j], ahf[i], bhf[j]);
        }
        __syncthreads();
    }

    const int erow = brow + wm + (lane >> 2);
    const int ecol = bcol + wn + (lane & 3) * 2;
#pragma unroll
    for (int i = 0; i < 4; i++) {
#pragma unroll
        for (int j = 0; j < 4; j++) {
            float* p0 = C + (size_t)(erow + i * 16) * Nglob + ecol + j * 8;
            float* p1 = C + (size_t)(erow + i * 16 + 8) * Nglob + ecol + j * 8;
            *(float2*)p0 = make_float2(acc[i][j][0], acc[i][j][1]);
            *(float2*)p1 = make_float2(acc[i][j][2], acc[i][j][3]);
        }
    }
}

// ==========================================================================
// fp32 -> fp16 hi/lo split
// ==========================================================================
__global__ __launch_bounds__(256) void convert_split(
    const float* __restrict__ x, __half* __restrict__ hi,
    __half* __restrict__ lo, int n4)
{
    int i = blockIdx.x * 256 + threadIdx.x;
    if (i >= n4) return;
    float4 v = ((const float4*)x)[i];
    float vals[4] = {v.x, v.y, v.z, v.w};
    __half hs[4], ls[4];
#pragma unroll
    for (int j = 0; j < 4; j++) {
        __half h = __float2half_rn(vals[j]);
        hs[j] = h;
        ls[j] = __float2half_rn(vals[j] - __half2float(h));
    }
    *(uint2*)(hi + i * 4) = *(uint2*)hs;
    *(uint2*)(lo + i * 4) = *(uint2*)ls;
}

// ==========================================================================
// W[K,N] fp32 -> W^T[N,K] fp16 (hi only)
// ==========================================================================
__global__ __launch_bounds__(256) void transpose_hi(
    const float* __restrict__ W, __half* __restrict__ th, int K, int N)
{
    __shared__ float t[32][33];
    const int bx = blockIdx.x * 32;
    const int by = blockIdx.y * 32;
    const int tx = threadIdx.x;
    const int ty = threadIdx.y;
#pragma unroll
    for (int i = 0; i < 32; i += 8)
        t[ty + i][tx] = W[(size_t)(by + ty + i) * N + bx + tx];
    __syncthreads();
#pragma unroll
    for (int i = 0; i < 32; i += 8) {
        float v = t[tx][ty + i];
        th[(size_t)(bx + ty + i) * K + by + tx] = __float2half_rn(v);
    }
}

// ==========================================================================
// HMMA flash attention: BR=128, BC=64, 8 warps, causal GQA.
// QK = (Qh+Ql)·Kh; PV = (Ph+Pl)·Vh. K/V hi-only. Heavy q-tiles first.
// Epilogue writes attn hi into g_ah. (unchanged from R16)
// ==========================================================================
#define FROW 272
#define FQ_H 0
#define FQ_L (128 * FROW)
#define FSTAGE0 (2 * 128 * FROW)          // 69632
#define FSTAGE_B (2 * 64 * FROW)          // 34816 (Kh, Vh)
#define FK_H 0
#define FV_H (64 * FROW)
#define FLASH_SMEM (FSTAGE0 + 2 * FSTAGE_B)   // 139264

__global__ __launch_bounds__(256, 1) void flash_hmma_kernel()
{
    extern __shared__ __align__(128) char smem[];
    const uint32_t sbase = smem_to_u32(smem);
    const int tid  = threadIdx.x;
    const int wid  = tid >> 5;
    const int lane = tid & 31;
    const int qt   = gridDim.x - 1 - blockIdx.x;   // heavy tiles launch first
    const int h    = blockIdx.y;
    const int kvh  = h >> 2;
    const int qbase = qt * 128;
    const int wr   = wid * 16;
    const int jlast = 2 * qt + 1;

    const __half* Qhg = g_qh + ((size_t)h * S_LEN + qbase) * HD;
    const __half* Qlg = g_ql + ((size_t)h * S_LEN + qbase) * HD;
    const __half* Khg = g_kh + (size_t)kvh * S_LEN * HD;
    const __half* Vhg = g_vh + (size_t)kvh * S_LEN * HD;

    {
#pragma unroll
        for (int t = 0; t < 8; t++) {
            int e = tid + t * 256;
            int r = e >> 4, c = e & 15;
            cp_async16(sbase + FQ_H + r * FROW + c * 16, Qhg + r * HD + c * 8);
        }
#pragma unroll
        for (int t = 0; t < 8; t++) {
            int e = tid + t * 256;
            int r = e >> 4, c = e & 15;
            cp_async16(sbase + FQ_L + r * FROW + c * 16, Qlg + r * HD + c * 8);
        }
    }

    auto load_stage = [&](int s, int jt) {
        const uint32_t stage = sbase + FSTAGE0 + s * FSTAGE_B;
        const int kbase = jt * 64;
        const __half* gs[2] = { Khg, Vhg };
        const uint32_t off[2] = { FK_H, FV_H };
#pragma unroll
        for (int m = 0; m < 2; m++) {
#pragma unroll
            for (int t = 0; t < 4; t++) {
                int e = tid + t * 256;
                int r = e >> 4, c = e & 15;
                cp_async16(stage + off[m] + r * FROW + c * 16,
                           gs[m] + (size_t)(kbase + r) * HD + c * 8);
            }
        }
    };

    load_stage(0, 0);
    CP_COMMIT();

    float oacc[16][4];
    float m0 = -1e30f, m1 = -1e30f, l0 = 0.0f, l1 = 0.0f;
#pragma unroll
    for (int nt = 0; nt < 16; nt++)
#pragma unroll
        for (int e = 0; e < 4; e++) oacc[nt][e] = 0.0f;

    const int rq = lane >> 2;
    const int cq = (lane & 3) * 2;
    const float s2scale = SCALE * LOG2E;

    for (int jt = 0; jt <= jlast; jt++) {
        if (jt + 1 <= jlast) { load_stage((jt + 1) & 1, jt + 1); CP_COMMIT(); CP_WAIT(1); }
        else                 { CP_WAIT(0); }
        __syncthreads();

        const bool active = (jt * 64 <= qbase + wr + 15);
        if (active) {
            const uint32_t stage = sbase + FSTAGE0 + (jt & 1) * FSTAGE_B;

            float sacc[8][4];
#pragma unroll
            for (int nt = 0; nt < 8; nt++)
#pragma unroll
                for (int e = 0; e < 4; e++) sacc[nt][e] = 0.0f;

            const int arow = wr + (lane & 15);
            const int acol16 = (lane >> 4) * 16;
            const int bl8 = lane & 7;
            const int bsel = ((lane >> 3) & 1) * 16;

#pragma unroll
            for (int kk = 0; kk < 8; kk++) {
                uint32_t ah[4], al[4];
                uint32_t qaddr = sbase + FQ_H + arow * FROW + kk * 32 + acol16;
                ldsm_x4(ah, qaddr);
                ldsm_x4(al, qaddr + FQ_L);
#pragma unroll
                for (int nt = 0; nt < 8; nt++) {
                    uint32_t bh[2];
                    uint32_t kaddr = stage + FK_H + (nt * 8 + bl8) * FROW + kk * 32 + bsel;
                    ldsm_x2(bh, kaddr);
                    mma16816(sacc[nt], ah, bh);
                    mma16816(sacc[nt], al, bh);
                }
            }

            const int row0 = qbase + wr + rq;
            if (jt >= 2 * qt) {
#pragma unroll
                for (int nt = 0; nt < 8; nt++) {
                    int col = jt * 64 + nt * 8 + cq;
#pragma unroll
                    for (int e = 0; e < 4; e++) {
                        int cc = col + (e & 1);
                        int rr = row0 + ((e >> 1) ? 8 : 0);
                        float sv = sacc[nt][e] * s2scale;
                        sacc[nt][e] = (cc > rr) ? -1e30f : sv;
                    }
                }
            } else {
#pragma unroll
                for (int nt = 0; nt < 8; nt++)
#pragma unroll
                    for (int e = 0; e < 4; e++) sacc[nt][e] *= s2scale;
            }

            float mx0 = -1e30f, mx1 = -1e30f;
#pragma unroll
            for (int nt = 0; nt < 8; nt++) {
                mx0 = fmaxf(mx0, fmaxf(sacc[nt][0], sacc[nt][1]));
                mx1 = fmaxf(mx1, fmaxf(sacc[nt][2], sacc[nt][3]));
            }
#pragma unroll
            for (int off = 1; off <= 2; off <<= 1) {
                mx0 = fmaxf(mx0, __shfl_xor_sync(0xffffffffu, mx0, off));
                mx1 = fmaxf(mx1, __shfl_xor_sync(0xffffffffu, mx1, off));
            }
            float mn0 = fmaxf(m0, mx0), mn1 = fmaxf(m1, mx1);
            float alpha0 = fast_exp2(m0 - mn0), alpha1 = fast_exp2(m1 - mn1);

            float rs0 = 0.0f, rs1 = 0.0f;
#pragma unroll
            for (int nt = 0; nt < 8; nt++) {
                sacc[nt][0] = fast_exp2(sacc[nt][0] - mn0);
                sacc[nt][1] = fast_exp2(sacc[nt][1] - mn0);
                sacc[nt][2] = fast_exp2(sacc[nt][2] - mn1);
                sacc[nt][3] = fast_exp2(sacc[nt][3] - mn1);
                rs0 += sacc[nt][0] + sacc[nt][1];
                rs1 += sacc[nt][2] + sacc[nt][3];
            }
#pragma unroll
            for (int off = 1; off <= 2; off <<= 1) {
                rs0 += __shfl_xor_sync(0xffffffffu, rs0, off);
                rs1 += __shfl_xor_sync(0xffffffffu, rs1, off);
            }
            l0 = l0 * alpha0 + rs0;
            l1 = l1 * alpha1 + rs1;
            m0 = mn0; m1 = mn1;

#pragma unroll
            for (int nt = 0; nt < 16; nt++) {
                oacc[nt][0] *= alpha0; oacc[nt][1] *= alpha0;
                oacc[nt][2] *= alpha1; oacc[nt][3] *= alpha1;
            }

            uint32_t ph[4][4], pl[4][4];
#pragma unroll
            for (int kt = 0; kt < 4; kt++) {
                const float* pA = sacc[2 * kt];
                const float* pB = sacc[2 * kt + 1];
                uint32_t h0 = packh2(pA[0], pA[1]);
                uint32_t h1 = packh2(pA[2], pA[3]);
                uint32_t h2 = packh2(pB[0], pB[1]);
                uint32_t h3 = packh2(pB[2], pB[3]);
                ph[kt][0] = h0; ph[kt][1] = h1; ph[kt][2] = h2; ph[kt][3] = h3;
                __half2 hh0 = *reinterpret_cast<__half2*>(&h0);
                __half2 hh1 = *reinterpret_cast<__half2*>(&h1);
                __half2 hh2 = *reinterpret_cast<__half2*>(&h2);
                __half2 hh3 = *reinterpret_cast<__half2*>(&h3);
                pl[kt][0] = packh2(pA[0] - __low2float(hh0), pA[1] - __high2float(hh0));
                pl[kt][1] = packh2(pA[2] - __low2float(hh1), pA[3] - __high2float(hh1));
                pl[kt][2] = packh2(pB[0] - __low2float(hh2), pB[1] - __high2float(hh2));
                pl[kt][3] = packh2(pB[2] - __low2float(hh3), pB[3] - __high2float(hh3));
            }

            const int vl16 = lane & 15;
#pragma unroll
            for (int kt = 0; kt < 4; kt++) {
#pragma unroll
                for (int nt = 0; nt < 16; nt++) {
                    uint32_t vh[2];
                    uint32_t vaddr = stage + FV_H + (kt * 16 + vl16) * FROW + nt * 16;
                    ldsm_x2_trans(vh, vaddr);
                    mma16816(oacc[nt], ph[kt], vh);
                    mma16816(oacc[nt], pl[kt], vh);
                }
            }
        }
        __syncthreads();
    }

    const float inv0 = 1.0f / l0;
    const float inv1 = 1.0f / l1;
    const int row0 = qbase + wr + (lane >> 2);
    const int colb = h * HD + (lane & 3) * 2;
#pragma unroll
    for (int nt = 0; nt < 16; nt++) {
        int col = colb + nt * 8;
        *(uint32_t*)(g_ah + (size_t)row0 * HID + col) =
            packh2(oacc[nt][0] * inv0, oacc[nt][1] * inv0);
        *(uint32_t*)(g_ah + (size_t)(row0 + 8) * HID + col) =
            packh2(oacc[nt][2] * inv1, oacc[nt][3] * inv1);
    }
}

// ==========================================================================
// launch
// ==========================================================================
extern "C" void kernel_launch(void* const* d_in, const int* in_sizes, int n_in,
                              void* d_out, int out_size)
{
    const int*   positions = (const int*)d_in[0];
    const float* hidden    = (const float*)d_in[1];
    const float* w_qkv     = (const float*)d_in[2];
    const float* w_o       = (const float*)d_in[3];
    float*       out       = (float*)d_out;

    void *p_ah, *p_al, *p_wqh, *p_woh;
    cudaGetSymbolAddress(&p_ah,  g_ah);
    cudaGetSymbolAddress(&p_al,  g_al);
    cudaGetSymbolAddress(&p_wqh, g_wqh);
    cudaGetSymbolAddress(&p_woh, g_woh);
    __half* ah  = (__half*)p_ah;
    __half* al  = (__half*)p_al;
    __half* wqh = (__half*)p_wqh;
    __half* woh = (__half*)p_woh;

    cudaFuncSetAttribute(gemm_qkv_rope,
                         cudaFuncAttributeMaxDynamicSharedMemorySize, GEMM2_SMEM);
    cudaFuncSetAttribute(gemm_hmma_hi,
                         cudaFuncAttributeMaxDynamicSharedMemorySize, GEMM1_SMEM);
    cudaFuncSetAttribute(flash_hmma_kernel,
                         cudaFuncAttributeMaxDynamicSharedMemorySize, FLASH_SMEM);

    // 1) operand prep: activation hi/lo, w_qkv^T hi, rope tables
    {
        int n4 = (S_LEN * HID) / 4;
        convert_split<<<(n4 + 255) / 256, 256>>>(hidden, ah, al, n4);
        dim3 tg(QKV_N / 32, HID / 32);
        transpose_hi<<<tg, dim3(32, 8)>>>(w_qkv, wqh, HID, QKV_N);
        rope_table<<<(S_LEN * 64) / 256, 256>>>(positions);
    }
    // 2) fused QKV projection + RoPE -> g_qh/g_ql/g_kh/g_vh directly
    {
        dim3 grid(QKV_N / 128, S_LEN / 128);
        gemm_qkv_rope<<<grid, 256, GEMM2_SMEM>>>(ah, al, wqh, HID);
    }
    // 3) HMMA flash attention -> writes attn hi into g_ah
    {
        dim3 grid(S_LEN / 128, NH);
        flash_hmma_kernel<<<grid, 256, FLASH_SMEM>>>();
    }
    // 4) O-GEMM weight prep
    {
        dim3 tg(HID / 32, QS / 32);
        transpose_hi<<<tg, dim3(32, 8)>>>(w_o, woh, QS, HID);
    }
    // 5) output projection (1-term fp16, BK=64)
    {
        dim3 grid(HID / 128, S_LEN / 128);
        gemm_hmma_hi<<<grid, 256, GEMM1_SMEM>>>(ah, woh, out, HID, QS);
    }
}